// round 3
// baseline (speedup 1.0000x reference)
#include <cuda_runtime.h>
#include <cstdint>

// Problem constants
#define B   4
#define T   8192
#define BT  32768     // B*T
#define E   1024      // n_embd
#define D   64        // d_head
#define M   8         // M_FEAT
#define F   16        // 2*M feature dim
#define SPLIT 32      // split-K over t for G accumulation
#define TCH (T/SPLIT) // 256 tokens per split chunk

// -------- scratch (device globals; no allocation) --------
__device__ float g_Wf[E * F];            // folded weights [k][16] (cols 0-7: q, 8-15: k)
__device__ float g_bf[F];                // folded biases
__device__ float g_qP[(size_t)BT * F];   // q features (cos|sin)/sqrt(8)
__device__ float g_Kp[(size_t)BT * F];   // k features
__device__ float g_Gpart[(size_t)SPLIT * B * F * E]; // 8 MB split-K partials
__device__ float g_G[(size_t)B * F * E]; // reduced G
__device__ float g_S[(size_t)B * F * D]; // S = G@Wv + kpsum*bv

// -------- packed f32x2 helpers --------
__device__ __forceinline__ uint64_t pack2(float lo, float hi) {
    uint64_t r;
    asm("mov.b64 %0, {%1, %2};" : "=l"(r) : "f"(lo), "f"(hi));
    return r;
}
__device__ __forceinline__ float2 unpack2(uint64_t v) {
    float2 r;
    asm("mov.b64 {%0, %1}, %2;" : "=f"(r.x), "=f"(r.y) : "l"(v));
    return r;
}
__device__ __forceinline__ void fma2(uint64_t& d, uint64_t a, uint64_t b) {
    asm("fma.rn.f32x2 %0, %1, %2, %0;" : "+l"(d) : "l"(a), "l"(b));
}

// ============================================================
// Kernel 0: fold weights  Wf = [Wq@w | Wk@w], bf = [bq@w | bk@w]
// ============================================================
__global__ void k_fold(const float* __restrict__ Wq, const float* __restrict__ bq,
                       const float* __restrict__ Wk, const float* __restrict__ bk,
                       const float* __restrict__ w) {
    int idx = blockIdx.x * blockDim.x + threadIdx.x;  // 0 .. 16383
    if (idx < E * F) {
        int j = idx & 15;
        int k = idx >> 4;
        const float* W = (j < 8) ? Wq : Wk;
        int jm = j & 7;
        float s = 0.0f;
#pragma unroll 8
        for (int d = 0; d < D; d++) s += W[k * D + d] * w[d * M + jm];
        g_Wf[k * F + j] = s;
    }
    if (blockIdx.x == 0 && idx < F) {
        int jm = idx & 7;
        const float* bb = (idx < 8) ? bq : bk;
        float s = 0.0f;
#pragma unroll 8
        for (int d = 0; d < D; d++) s += bb[d] * w[d * M + jm];
        g_bf[idx] = s;
    }
}

// ============================================================
// Kernel 1: features.  p = x @ Wf + bf  (16 cols), then
// qP = [cos(p_q), sin(p_q)]/sqrt(8), Kp = [cos(p_k), sin(p_k)]/sqrt(8)
// 128 blocks x 128 threads, 2 rows per thread.
// ============================================================
__device__ __forceinline__ void feat_store(int row, const uint64_t* acc) {
    float p[16];
#pragma unroll
    for (int j = 0; j < 8; j++) {
        float2 t = unpack2(acc[j]);
        p[2 * j]     = t.x;
        p[2 * j + 1] = t.y;
    }
    const float inv = 0.35355339059327376f;  // 1/sqrt(8)
    float qcv[8], qsv[8], kcv[8], ksv[8];
#pragma unroll
    for (int j = 0; j < 8; j++) {
        float s, c;
        sincosf(p[j], &s, &c);
        qcv[j] = c * inv; qsv[j] = s * inv;
    }
#pragma unroll
    for (int j = 0; j < 8; j++) {
        float s, c;
        sincosf(p[8 + j], &s, &c);
        kcv[j] = c * inv; ksv[j] = s * inv;
    }
    float4* qd = (float4*)(g_qP + (size_t)row * F);
    qd[0] = make_float4(qcv[0], qcv[1], qcv[2], qcv[3]);
    qd[1] = make_float4(qcv[4], qcv[5], qcv[6], qcv[7]);
    qd[2] = make_float4(qsv[0], qsv[1], qsv[2], qsv[3]);
    qd[3] = make_float4(qsv[4], qsv[5], qsv[6], qsv[7]);
    float4* kd = (float4*)(g_Kp + (size_t)row * F);
    kd[0] = make_float4(kcv[0], kcv[1], kcv[2], kcv[3]);
    kd[1] = make_float4(kcv[4], kcv[5], kcv[6], kcv[7]);
    kd[2] = make_float4(ksv[0], ksv[1], ksv[2], ksv[3]);
    kd[3] = make_float4(ksv[4], ksv[5], ksv[6], ksv[7]);
}

__global__ void __launch_bounds__(128) k_feat(const float* __restrict__ x) {
    extern __shared__ float sWf[];  // E*F floats = 64 KB
    __shared__ float sbf[F];
    for (int i = threadIdx.x; i < E * F / 4; i += 128)
        ((float4*)sWf)[i] = ((const float4*)g_Wf)[i];
    if (threadIdx.x < F) sbf[threadIdx.x] = g_bf[threadIdx.x];
    __syncthreads();

    int row0 = blockIdx.x * 256 + threadIdx.x;
    int row1 = row0 + 128;
    uint64_t acc0[8], acc1[8];
#pragma unroll
    for (int j = 0; j < 8; j++) {
        uint64_t bj = pack2(sbf[2 * j], sbf[2 * j + 1]);
        acc0[j] = bj;
        acc1[j] = bj;
    }
    const float4* x0 = (const float4*)(x + (size_t)row0 * E);
    const float4* x1 = (const float4*)(x + (size_t)row1 * E);

#pragma unroll 2
    for (int kq = 0; kq < E / 4; kq++) {
        float4 a = x0[kq];
        float4 b = x1[kq];
        float av[4] = {a.x, a.y, a.z, a.w};
        float bv[4] = {b.x, b.y, b.z, b.w};
        const float* wbase = sWf + kq * 4 * F;
#pragma unroll
        for (int u = 0; u < 4; u++) {
            uint64_t pa = pack2(av[u], av[u]);
            uint64_t pb = pack2(bv[u], bv[u]);
            const ulonglong2* wrow = (const ulonglong2*)(wbase + u * F);
#pragma unroll
            for (int q = 0; q < 4; q++) {
                ulonglong2 wv = wrow[q];
                fma2(acc0[2 * q],     pa, wv.x);
                fma2(acc0[2 * q + 1], pa, wv.y);
                fma2(acc1[2 * q],     pb, wv.x);
                fma2(acc1[2 * q + 1], pb, wv.y);
            }
        }
    }
    feat_store(row0, acc0);
    feat_store(row1, acc1);
}

// ============================================================
// Kernel 2: split-K partials of  G[b,16,1024] = Kp^T @ x (per batch)
// grid (SPLIT, B), 256 threads, 4 cols/thread, t-chunk = 256.
// ============================================================
__global__ void __launch_bounds__(256) k_gpart(const float* __restrict__ x) {
    __shared__ float sKp[TCH * F];  // 16 KB
    int s = blockIdx.x;
    int b = blockIdx.y;
    int t0 = s * TCH;

    const float4* kpsrc = (const float4*)(g_Kp + ((size_t)b * T + t0) * F);
    for (int i = threadIdx.x; i < TCH * F / 4; i += 256)
        ((float4*)sKp)[i] = kpsrc[i];
    __syncthreads();

    uint64_t acc[8][4];
#pragma unroll
    for (int p = 0; p < 8; p++)
#pragma unroll
        for (int c = 0; c < 4; c++) acc[p][c] = 0ull;

    const float4* xp = (const float4*)(x + ((size_t)b * T + t0) * E) + threadIdx.x;

#pragma unroll 2
    for (int t = 0; t < TCH; t++) {
        float4 xv = xp[t * (E / 4)];
        const ulonglong2* kr = (const ulonglong2*)(sKp + t * F);
        ulonglong2 k0 = kr[0], k1 = kr[1], k2 = kr[2], k3 = kr[3];
        uint64_t kp[8] = {k0.x, k0.y, k1.x, k1.y, k2.x, k2.y, k3.x, k3.y};
        float xa[4] = {xv.x, xv.y, xv.z, xv.w};
#pragma unroll
        for (int c = 0; c < 4; c++) {
            uint64_t xc = pack2(xa[c], xa[c]);
#pragma unroll
            for (int p = 0; p < 8; p++) fma2(acc[p][c], kp[p], xc);
        }
    }

    // write partials, coalesced float4 per feature row
    float* dst = g_Gpart + (((size_t)s * B + b) * F) * E + threadIdx.x * 4;
#pragma unroll
    for (int p = 0; p < 8; p++) {
        float2 u0 = unpack2(acc[p][0]);
        float2 u1 = unpack2(acc[p][1]);
        float2 u2 = unpack2(acc[p][2]);
        float2 u3 = unpack2(acc[p][3]);
        ((float4*)(dst + (size_t)(2 * p) * E))[0]     = make_float4(u0.x, u1.x, u2.x, u3.x);
        ((float4*)(dst + (size_t)(2 * p + 1) * E))[0] = make_float4(u0.y, u1.y, u2.y, u3.y);
    }
}

// ============================================================
// Kernel 3a: reduce split-K partials -> G (deterministic fixed order)
// ============================================================
__global__ void k_gred() {
    int i = blockIdx.x * 256 + threadIdx.x;  // < B*F*E = 65536
    float s = 0.0f;
#pragma unroll 8
    for (int sp = 0; sp < SPLIT; sp++)
        s += g_Gpart[(size_t)sp * (B * F * E) + i];
    g_G[i] = s;
}

// ============================================================
// Kernel 3b: S[b,f,:] = G[b,f,:] @ Wv + (sum_t Kp[b,t,f]) * bv
// grid (16, 4) = (f, b), 128 threads.
// ============================================================
__global__ void __launch_bounds__(128) k_s(const float* __restrict__ Wv,
                                           const float* __restrict__ bv) {
    int f = blockIdx.x;
    int b = blockIdx.y;
    __shared__ float sG[E];
    __shared__ float red[128];

    const float4* gsrc = (const float4*)(g_G + ((size_t)b * F + f) * E);
    for (int i = threadIdx.x; i < E / 4; i += 128)
        ((float4*)sG)[i] = gsrc[i];

    // kpsum: deterministic per-thread sequential + tree reduce
    float ks = 0.0f;
    for (int t = threadIdx.x; t < T; t += 128)
        ks += g_Kp[((size_t)b * T + t) * F + f];
    red[threadIdx.x] = ks;
    __syncthreads();
    for (int off = 64; off > 0; off >>= 1) {
        if (threadIdx.x < off) red[threadIdx.x] += red[threadIdx.x + off];
        __syncthreads();
    }
    float kpsum = red[0];

    if (threadIdx.x < D) {
        int n = threadIdx.x;
        float acc = kpsum * bv[n];
#pragma unroll 4
        for (int k = 0; k < E; k++)
            acc += sG[k] * Wv[k * D + n];
        g_S[((size_t)b * F + f) * D + n] = acc;
    }
}

// ============================================================
// Kernel 4: y[b,t,:] = qP[b,t,:] @ S[b]   (128 blocks x 256 threads)
// ============================================================
__global__ void __launch_bounds__(256) k_y(float* __restrict__ y) {
    __shared__ float sS[F * D];  // 4 KB
    int row = blockIdx.x * 256 + threadIdx.x;
    int b = (blockIdx.x * 256) >> 13;  // 256 | 8192, so all rows in block share b
    const float4* ssrc = (const float4*)(g_S + (size_t)b * F * D);
    for (int i = threadIdx.x; i < F * D / 4; i += 256)
        ((float4*)sS)[i] = ssrc[i];
    __syncthreads();

    const float4* qsrc = (const float4*)(g_qP + (size_t)row * F);
    float4 q0 = qsrc[0], q1 = qsrc[1], q2 = qsrc[2], q3 = qsrc[3];
    float qv[16] = {q0.x, q0.y, q0.z, q0.w, q1.x, q1.y, q1.z, q1.w,
                    q2.x, q2.y, q2.z, q2.w, q3.x, q3.y, q3.z, q3.w};

    uint64_t acc[32];
#pragma unroll
    for (int p = 0; p < 32; p++) acc[p] = 0ull;

#pragma unroll
    for (int f = 0; f < F; f++) {
        uint64_t qf = pack2(qv[f], qv[f]);
        const ulonglong2* sr = (const ulonglong2*)(sS + f * D);
#pragma unroll
        for (int p = 0; p < 16; p++) {
            ulonglong2 w = sr[p];
            fma2(acc[2 * p],     qf, w.x);
            fma2(acc[2 * p + 1], qf, w.y);
        }
    }

    float4* dst = (float4*)(y + (size_t)row * D);
#pragma unroll
    for (int p = 0; p < 16; p++) {
        float2 a = unpack2(acc[2 * p]);
        float2 c = unpack2(acc[2 * p + 1]);
        dst[p] = make_float4(a.x, a.y, c.x, c.y);
    }
}

// ============================================================
extern "C" void kernel_launch(void* const* d_in, const int* in_sizes, int n_in,
                              void* d_out, int out_size) {
    const float* x  = (const float*)d_in[0];
    const float* w  = (const float*)d_in[1];
    const float* Wq = (const float*)d_in[2];
    const float* bq = (const float*)d_in[3];
    const float* Wk = (const float*)d_in[4];
    const float* bk = (const float*)d_in[5];
    const float* Wv = (const float*)d_in[6];
    const float* bv = (const float*)d_in[7];
    float* y = (float*)d_out;

    cudaFuncSetAttribute(k_feat, cudaFuncAttributeMaxDynamicSharedMemorySize, E * F * 4);

    k_fold<<<64, 256>>>(Wq, bq, Wk, bk, w);
    k_feat<<<128, 128, E * F * 4>>>(x);
    dim3 g2(SPLIT, B);
    k_gpart<<<g2, 256>>>(x);
    k_gred<<<256, 256>>>();
    dim3 g3(16, 4);
    k_s<<<g3, 128>>>(Wv, bv);
    k_y<<<128, 256>>>(y);
}

// round 5
// speedup vs baseline: 2.0750x; 2.0750x over previous
#include <cuda_runtime.h>
#include <cstdint>

// Problem constants
#define B   4
#define T   8192
#define BT  32768     // B*T
#define E   1024      // n_embd
#define D   64        // d_head
#define M   8         // M_FEAT
#define F   16        // 2*M feature dim
#define CH  128       // tokens per fused block
#define NBLK (BT/CH)  // 256 blocks
#define SPB (T/CH)    // 64 chunks per batch

// -------- scratch (device globals; no allocation) --------
__device__ __align__(16) float g_Wf[E * F];            // folded weights [col][16]
__device__ __align__(16) float g_bf[F];                // folded biases
__device__ __align__(16) float g_qP[(size_t)BT * F];   // q features (cos|sin)/sqrt(8)
__device__ __align__(16) float g_Gpart[(size_t)NBLK * F * E]; // 16 MB split partials
__device__ __align__(16) float g_kps[NBLK * F];        // per-block Kp column sums
__device__ __align__(16) float g_S[B * F * D];         // S = G@Wv + kpsum*bv

// -------- packed f32x2 helpers --------
__device__ __forceinline__ uint64_t pack2(float lo, float hi) {
    uint64_t r;
    asm("mov.b64 %0, {%1, %2};" : "=l"(r) : "f"(lo), "f"(hi));
    return r;
}
__device__ __forceinline__ float2 unpack2(uint64_t v) {
    float2 r;
    asm("mov.b64 {%0, %1}, %2;" : "=f"(r.x), "=f"(r.y) : "l"(v));
    return r;
}
__device__ __forceinline__ void fma2(uint64_t& d, uint64_t a, uint64_t b) {
    asm("fma.rn.f32x2 %0, %1, %2, %0;" : "+l"(d) : "l"(a), "l"(b));
}

// ============================================================
// Kernel 0: fold weights  Wf = [Wq@w | Wk@w], bf = [bq@w | bk@w]
// ============================================================
__global__ void k_fold(const float* __restrict__ Wq, const float* __restrict__ bq,
                       const float* __restrict__ Wk, const float* __restrict__ bk,
                       const float* __restrict__ w) {
    int idx = blockIdx.x * blockDim.x + threadIdx.x;  // 0 .. 16383
    if (idx < E * F) {
        int j = idx & 15;
        int k = idx >> 4;
        const float* W = (j < 8) ? Wq : Wk;
        int jm = j & 7;
        float s = 0.0f;
#pragma unroll 8
        for (int d = 0; d < D; d++) s += W[k * D + d] * w[d * M + jm];
        g_Wf[k * F + j] = s;
    }
    if (blockIdx.x == 0 && idx < F) {
        int jm = idx & 7;
        const float* bb = (idx < 8) ? bq : bk;
        float s = 0.0f;
#pragma unroll 8
        for (int d = 0; d < D; d++) s += bb[d] * w[d * M + jm];
        g_bf[idx] = s;
    }
}

// ============================================================
// Fused kernel: per block of 128 tokens
//  pass1: p = x@Wf + bf (coalesced via smem staging), features
//         -> qP to global, Kp to smem, kpsum partial to global
//  pass2: Gpart[blk] = Kp^T @ x_chunk (x coalesced per-thread cols)
// ============================================================
__global__ void __launch_bounds__(256, 2) k_fused(const float* __restrict__ x) {
    __shared__ __align__(16) float sX[32 * 129];   // transposed x tile, pad for banks
    __shared__ __align__(16) float sW[32 * 16];    // weight chunk
    __shared__ __align__(16) float sP[16 * 128];   // partial p from h=1 (layout [j][tok])
    __shared__ __align__(16) float sKp[CH * 16];   // k features
    __shared__ __align__(16) float sbf[16];

    int tid = threadIdx.x;
    int blk = blockIdx.x;
    int row0 = blk * CH;
    int tok = tid & 127;
    int h = tid >> 7;

    if (tid < 16) sbf[tid] = g_bf[tid];

    uint64_t acc[8];
#pragma unroll
    for (int j = 0; j < 8; j++) acc[j] = 0ull;

    const float4* xg = (const float4*)x;
    int cbase = h * 16;

    // ---- pass 1: 32 chunks of 32 columns ----
    for (int ch = 0; ch < 32; ch++) {
        __syncthreads();
        // cooperative coalesced load + transpose: x[128 tok][32 cols] -> sX[col][tok]
#pragma unroll
        for (int q = 0; q < 4; q++) {
            int idx = q * 256 + tid;
            int t = idx >> 3, c4 = idx & 7;
            float4 v = xg[(size_t)(row0 + t) * (E / 4) + ch * 8 + c4];
            sX[(c4 * 4 + 0) * 129 + t] = v.x;
            sX[(c4 * 4 + 1) * 129 + t] = v.y;
            sX[(c4 * 4 + 2) * 129 + t] = v.z;
            sX[(c4 * 4 + 3) * 129 + t] = v.w;
        }
        if (tid < 128) ((float4*)sW)[tid] = ((const float4*)g_Wf)[ch * 128 + tid];
        __syncthreads();
        // compute: thread (tok, h) handles cols [h*16, h*16+16)
#pragma unroll
        for (int c = 0; c < 16; c++) {
            float xv = sX[(cbase + c) * 129 + tok];
            uint64_t xx = pack2(xv, xv);
            const ulonglong2* wr = (const ulonglong2*)(sW + (cbase + c) * 16);
#pragma unroll
            for (int q = 0; q < 4; q++) {
                ulonglong2 wv = wr[q];
                fma2(acc[2 * q],     xx, wv.x);
                fma2(acc[2 * q + 1], xx, wv.y);
            }
        }
    }

    // ---- combine halves, sincos, store features ----
    __syncthreads();
    if (h == 1) {
#pragma unroll
        for (int j = 0; j < 8; j++) {
            float2 v = unpack2(acc[j]);
            sP[(2 * j) * 128 + tok]     = v.x;
            sP[(2 * j + 1) * 128 + tok] = v.y;
        }
    }
    __syncthreads();
    if (h == 0) {
        float p[16];
#pragma unroll
        for (int j = 0; j < 8; j++) {
            float2 v = unpack2(acc[j]);
            p[2 * j]     = v.x + sP[(2 * j) * 128 + tok]     + sbf[2 * j];
            p[2 * j + 1] = v.y + sP[(2 * j + 1) * 128 + tok] + sbf[2 * j + 1];
        }
        const float inv = 0.35355339059327376f;  // 1/sqrt(8)
        float qc[8], qs[8], kc[8], ks[8];
#pragma unroll
        for (int j = 0; j < 8; j++) {
            float s, c;
            __sincosf(p[j], &s, &c);
            qc[j] = c * inv; qs[j] = s * inv;
        }
#pragma unroll
        for (int j = 0; j < 8; j++) {
            float s, c;
            __sincosf(p[8 + j], &s, &c);
            kc[j] = c * inv; ks[j] = s * inv;
        }
        float4* qd = (float4*)(g_qP + (size_t)(row0 + tok) * F);
        qd[0] = make_float4(qc[0], qc[1], qc[2], qc[3]);
        qd[1] = make_float4(qc[4], qc[5], qc[6], qc[7]);
        qd[2] = make_float4(qs[0], qs[1], qs[2], qs[3]);
        qd[3] = make_float4(qs[4], qs[5], qs[6], qs[7]);
        float4* kd = (float4*)(sKp + tok * 16);
        kd[0] = make_float4(kc[0], kc[1], kc[2], kc[3]);
        kd[1] = make_float4(kc[4], kc[5], kc[6], kc[7]);
        kd[2] = make_float4(ks[0], ks[1], ks[2], ks[3]);
        kd[3] = make_float4(ks[4], ks[5], ks[6], ks[7]);
    }
    __syncthreads();

    // kpsum partial (deterministic fixed order)
    if (tid < 16) {
        float s = 0.0f;
        for (int t = 0; t < CH; t++) s += sKp[t * 16 + tid];
        g_kps[blk * 16 + tid] = s;
    }

    // ---- pass 2: Gpart = Kp^T @ x_chunk, thread owns 4 columns ----
    uint64_t ga[8][4];
#pragma unroll
    for (int p2 = 0; p2 < 8; p2++)
#pragma unroll
        for (int c = 0; c < 4; c++) ga[p2][c] = 0ull;

    const float4* xp = (const float4*)(x + (size_t)row0 * E) + tid;

    for (int t0 = 0; t0 < CH; t0 += 4) {
        float4 v[4];
#pragma unroll
        for (int u = 0; u < 4; u++) v[u] = xp[(size_t)(t0 + u) * (E / 4)];
#pragma unroll
        for (int u = 0; u < 4; u++) {
            const ulonglong2* kr = (const ulonglong2*)(sKp + (t0 + u) * 16);
            ulonglong2 k0 = kr[0], k1 = kr[1], k2 = kr[2], k3 = kr[3];
            uint64_t kp[8] = {k0.x, k0.y, k1.x, k1.y, k2.x, k2.y, k3.x, k3.y};
            float xa[4] = {v[u].x, v[u].y, v[u].z, v[u].w};
#pragma unroll
            for (int c = 0; c < 4; c++) {
                uint64_t xc = pack2(xa[c], xa[c]);
#pragma unroll
                for (int p2 = 0; p2 < 8; p2++) fma2(ga[p2][c], kp[p2], xc);
            }
        }
    }

    float* dst = g_Gpart + (size_t)blk * F * E + tid * 4;
#pragma unroll
    for (int p2 = 0; p2 < 8; p2++) {
        float2 u0 = unpack2(ga[p2][0]);
        float2 u1 = unpack2(ga[p2][1]);
        float2 u2 = unpack2(ga[p2][2]);
        float2 u3 = unpack2(ga[p2][3]);
        ((float4*)(dst + (size_t)(2 * p2) * E))[0]     = make_float4(u0.x, u1.x, u2.x, u3.x);
        ((float4*)(dst + (size_t)(2 * p2 + 1) * E))[0] = make_float4(u0.y, u1.y, u2.y, u3.y);
    }
}

// ============================================================
// k_s: reduce Gpart -> G row, then S[b,f,:] = G@Wv + kpsum*bv
// grid (16, 4) = (f, b), 128 threads
// ============================================================
__global__ void __launch_bounds__(128) k_s(const float* __restrict__ Wv,
                                           const float* __restrict__ bv) {
    int f = blockIdx.x;
    int b = blockIdx.y;
    int tid = threadIdx.x;
    __shared__ __align__(16) float sG[E];
    __shared__ float skr[64];
    __shared__ float s2[64];

    // phase 1: sum split partials into sG (fixed order over sp)
    float4 a0 = make_float4(0.f, 0.f, 0.f, 0.f);
    float4 a1 = make_float4(0.f, 0.f, 0.f, 0.f);
    for (int sp = 0; sp < SPB; sp++) {
        const float4* base = (const float4*)(g_Gpart + ((size_t)(b * SPB + sp) * F + f) * E);
        float4 v0 = base[tid];
        float4 v1 = base[tid + 128];
        a0.x += v0.x; a0.y += v0.y; a0.z += v0.z; a0.w += v0.w;
        a1.x += v1.x; a1.y += v1.y; a1.z += v1.z; a1.w += v1.w;
    }
    ((float4*)sG)[tid] = a0;
    ((float4*)sG)[tid + 128] = a1;

    if (tid < 64) skr[tid] = g_kps[(b * SPB + tid) * 16 + f];
    __syncthreads();

    // phase 2: GEMV, thread (d, half)
    int d = tid & 63, h = tid >> 6;
    float acc = 0.0f;
    const float* gp = sG + h * 512;
    const float* wp = Wv + (size_t)h * 512 * D + d;
#pragma unroll 8
    for (int e = 0; e < 512; e++) acc += gp[e] * wp[(size_t)e * D];

    if (h == 1) s2[d] = acc;
    __syncthreads();
    if (h == 0) {
        float kpsum = 0.0f;
        for (int i = 0; i < 64; i++) kpsum += skr[i];
        g_S[((size_t)b * F + f) * D + d] = acc + s2[d] + kpsum * bv[d];
    }
}

// ============================================================
// k_y: y[b,t,:] = qP[b,t,:] @ S[b]
// ============================================================
__global__ void __launch_bounds__(256) k_y(float* __restrict__ y) {
    __shared__ __align__(16) float sS[F * D];  // 4 KB
    int row = blockIdx.x * 256 + threadIdx.x;
    int b = (blockIdx.x * 256) >> 13;  // 256 | 8192, all rows in block share b
    const float4* ssrc = (const float4*)(g_S + (size_t)b * F * D);
    for (int i = threadIdx.x; i < F * D / 4; i += 256)
        ((float4*)sS)[i] = ssrc[i];
    __syncthreads();

    const float4* qsrc = (const float4*)(g_qP + (size_t)row * F);
    float4 q0 = qsrc[0], q1 = qsrc[1], q2 = qsrc[2], q3 = qsrc[3];
    float qv[16] = {q0.x, q0.y, q0.z, q0.w, q1.x, q1.y, q1.z, q1.w,
                    q2.x, q2.y, q2.z, q2.w, q3.x, q3.y, q3.z, q3.w};

    uint64_t acc[32];
#pragma unroll
    for (int p = 0; p < 32; p++) acc[p] = 0ull;

#pragma unroll
    for (int f = 0; f < F; f++) {
        uint64_t qf = pack2(qv[f], qv[f]);
        const ulonglong2* sr = (const ulonglong2*)(sS + f * D);
#pragma unroll
        for (int p = 0; p < 16; p++) {
            ulonglong2 w = sr[p];
            fma2(acc[2 * p],     qf, w.x);
            fma2(acc[2 * p + 1], qf, w.y);
        }
    }

    float4* dst = (float4*)(y + (size_t)row * D);
#pragma unroll
    for (int p = 0; p < 16; p++) {
        float2 a = unpack2(acc[2 * p]);
        float2 c = unpack2(acc[2 * p + 1]);
        dst[p] = make_float4(a.x, a.y, c.x, c.y);
    }
}

// ============================================================
extern "C" void kernel_launch(void* const* d_in, const int* in_sizes, int n_in,
                              void* d_out, int out_size) {
    const float* x  = (const float*)d_in[0];
    const float* w  = (const float*)d_in[1];
    const float* Wq = (const float*)d_in[2];
    const float* bq = (const float*)d_in[3];
    const float* Wk = (const float*)d_in[4];
    const float* bk = (const float*)d_in[5];
    const float* Wv = (const float*)d_in[6];
    const float* bv = (const float*)d_in[7];
    float* y = (float*)d_out;

    k_fold<<<64, 256>>>(Wq, bq, Wk, bk, w);
    k_fused<<<NBLK, 256>>>(x);
    dim3 gs(16, 4);
    k_s<<<gs, 128>>>(Wv, bv);
    k_y<<<128, 256>>>(y);
}

// round 6
// speedup vs baseline: 2.2508x; 1.0847x over previous
#include <cuda_runtime.h>
#include <cstdint>

// Problem constants
#define B   4
#define T   8192
#define BT  32768     // B*T
#define E   1024      // n_embd
#define D   64        // d_head
#define M   8         // M_FEAT
#define F   16        // 2*M feature dim
#define CH  128       // tokens per fused block
#define NBLK (BT/CH)  // 256 blocks
#define SPB (T/CH)    // 64 chunks per batch
#define KPAD 20       // sKp row stride (pad vs 16 to kill bank conflicts)

// -------- scratch (device globals; no allocation) --------
__device__ __align__(16) float g_Wf[E * F];            // folded weights [k][16]
__device__ __align__(16) float g_bf[F];                // folded biases
__device__ __align__(16) float g_qP[(size_t)BT * F];   // q features (cos|sin)/sqrt(8)
__device__ __align__(16) float g_Gpart[(size_t)NBLK * F * E]; // 16 MB split partials
__device__ __align__(16) float g_G[(size_t)B * F * E];        // reduced G
__device__ __align__(16) float g_kps[NBLK * F];        // per-block Kp column sums
__device__ __align__(16) float g_S[B * F * D];         // S = G@Wv + kpsum*bv

// -------- packed f32x2 helpers --------
__device__ __forceinline__ uint64_t pack2(float lo, float hi) {
    uint64_t r;
    asm("mov.b64 %0, {%1, %2};" : "=l"(r) : "f"(lo), "f"(hi));
    return r;
}
__device__ __forceinline__ float2 unpack2(uint64_t v) {
    float2 r;
    asm("mov.b64 {%0, %1}, %2;" : "=f"(r.x), "=f"(r.y) : "l"(v));
    return r;
}
__device__ __forceinline__ void fma2(uint64_t& d, uint64_t a, uint64_t b) {
    asm("fma.rn.f32x2 %0, %1, %2, %0;" : "+l"(d) : "l"(a), "l"(b));
}

// ============================================================
// Kernel 0: fold weights  Wf = [Wq@w | Wk@w], bf = [bq@w | bk@w]
// ============================================================
__global__ void k_fold(const float* __restrict__ Wq, const float* __restrict__ bq,
                       const float* __restrict__ Wk, const float* __restrict__ bk,
                       const float* __restrict__ w) {
    int idx = blockIdx.x * blockDim.x + threadIdx.x;  // 0 .. 16383
    if (idx < E * F) {
        int j = idx & 15;
        int k = idx >> 4;
        const float* W = (j < 8) ? Wq : Wk;
        int jm = j & 7;
        float s = 0.0f;
#pragma unroll 8
        for (int d = 0; d < D; d++) s += W[k * D + d] * w[d * M + jm];
        g_Wf[k * F + j] = s;
    }
    if (blockIdx.x == 0 && idx < F) {
        int jm = idx & 7;
        const float* bb = (idx < 8) ? bq : bk;
        float s = 0.0f;
#pragma unroll 8
        for (int d = 0; d < D; d++) s += bb[d] * w[d * M + jm];
        g_bf[idx] = s;
    }
}

// ============================================================
// Fused kernel, 256 blocks x 256 threads, dynamic smem:
//   region A [16384 floats]: pass1 staging (sX [32][132] + sW [32][16]),
//                            later aliased as sPart [8][16][128]
//   sKp  [128][KPAD]
//   sbf  [16]
// pass1: thread (tg,h) owns 4 tokens x 4 cols per 32-col chunk, 8-way k-split
// reduce: combine h-partials, sincos distributed over all threads
// pass2: Gpart = Kp^T @ x_chunk, thread owns 4 e-columns
// ============================================================
#define SMEM_FLOATS (16384 + CH * KPAD + 16)

__global__ void __launch_bounds__(256, 2) k_fused(const float* __restrict__ x) {
    extern __shared__ __align__(16) float smem[];
    float* sX    = smem;            // [32][132] = 4224 floats
    float* sW    = smem + 4224;     // [32][16]  = 512 floats
    float* sPart = smem;            // [8][16][128] = 16384 floats (alias, after pass1)
    float* sKp   = smem + 16384;    // [128][KPAD]
    float* sbf   = smem + 16384 + CH * KPAD;

    int tid = threadIdx.x;
    int blk = blockIdx.x;
    int row0 = blk * CH;
    int tg = tid & 31;   // token group: tokens 4tg..4tg+3
    int h  = tid >> 5;   // k-split 0..7 (cols 4h..4h+3 within each chunk)

    if (tid < 16) sbf[tid] = g_bf[tid];

    uint64_t acc[4][8];  // [token u][feature pair q]
#pragma unroll
    for (int u = 0; u < 4; u++)
#pragma unroll
        for (int q = 0; q < 8; q++) acc[u][q] = 0ull;

    const float4* xg = (const float4*)x;

    // ---- pass 1: 32 chunks of 32 columns ----
    for (int ch = 0; ch < 32; ch++) {
        __syncthreads();
        // stage x[128 tok][32 cols] transposed -> sX[col][tok] (pad 132)
#pragma unroll
        for (int q = 0; q < 4; q++) {
            int idx = q * 256 + tid;
            int t = idx >> 3, c4 = idx & 7;
            float4 v = xg[(size_t)(row0 + t) * (E / 4) + ch * 8 + c4];
            sX[(c4 * 4 + 0) * 132 + t] = v.x;
            sX[(c4 * 4 + 1) * 132 + t] = v.y;
            sX[(c4 * 4 + 2) * 132 + t] = v.z;
            sX[(c4 * 4 + 3) * 132 + t] = v.w;
        }
        if (tid < 128) ((float4*)sW)[tid] = ((const float4*)g_Wf)[ch * 128 + tid];
        __syncthreads();

#pragma unroll
        for (int c = 0; c < 4; c++) {
            int k = 4 * h + c;
            float4 xv = *(const float4*)(sX + k * 132 + 4 * tg);     // 4 tokens
            const ulonglong2* wr = (const ulonglong2*)(sW + k * 16); // broadcast
            ulonglong2 w0 = wr[0], w1 = wr[1], w2 = wr[2], w3 = wr[3];
            uint64_t wv[8] = {w0.x, w0.y, w1.x, w1.y, w2.x, w2.y, w3.x, w3.y};
            float xa[4] = {xv.x, xv.y, xv.z, xv.w};
#pragma unroll
            for (int u = 0; u < 4; u++) {
                uint64_t xx = pack2(xa[u], xa[u]);
#pragma unroll
                for (int q = 0; q < 8; q++) fma2(acc[u][q], wv[q], xx);
            }
        }
    }

    // ---- write k-split partials: sPart[h][f][tok] ----
    __syncthreads();
#pragma unroll
    for (int q = 0; q < 8; q++) {
        float2 v0 = unpack2(acc[0][q]);
        float2 v1 = unpack2(acc[1][q]);
        float2 v2 = unpack2(acc[2][q]);
        float2 v3 = unpack2(acc[3][q]);
        *(float4*)(sPart + h * 2048 + (2 * q) * 128 + 4 * tg)     = make_float4(v0.x, v1.x, v2.x, v3.x);
        *(float4*)(sPart + h * 2048 + (2 * q + 1) * 128 + 4 * tg) = make_float4(v0.y, v1.y, v2.y, v3.y);
    }
    __syncthreads();

    // ---- combine + sincos: thread (tok, g); g=0 -> q feats, g=1 -> k feats ----
    {
        int tok = tid & 127;
        int g = tid >> 7;
        float p[8];
#pragma unroll
        for (int j = 0; j < 8; j++) {
            int f = 8 * g + j;
            float s = 0.0f;
#pragma unroll
            for (int h2 = 0; h2 < 8; h2++) s += sPart[h2 * 2048 + f * 128 + tok];
            p[j] = s + sbf[f];
        }
        const float inv = 0.35355339059327376f;  // 1/sqrt(8)
        float cv[8], sv[8];
#pragma unroll
        for (int j = 0; j < 8; j++) {
            float s, c;
            __sincosf(p[j], &s, &c);
            cv[j] = c * inv; sv[j] = s * inv;
        }
        if (g == 0) {
            float4* qd = (float4*)(g_qP + (size_t)(row0 + tok) * F);
            qd[0] = make_float4(cv[0], cv[1], cv[2], cv[3]);
            qd[1] = make_float4(cv[4], cv[5], cv[6], cv[7]);
            qd[2] = make_float4(sv[0], sv[1], sv[2], sv[3]);
            qd[3] = make_float4(sv[4], sv[5], sv[6], sv[7]);
        } else {
            float4* kd = (float4*)(sKp + tok * KPAD);
            kd[0] = make_float4(cv[0], cv[1], cv[2], cv[3]);
            kd[1] = make_float4(cv[4], cv[5], cv[6], cv[7]);
            kd[2] = make_float4(sv[0], sv[1], sv[2], sv[3]);
            kd[3] = make_float4(sv[4], sv[5], sv[6], sv[7]);
        }
    }
    __syncthreads();

    // kpsum partial (deterministic fixed order)
    if (tid < 16) {
        float s = 0.0f;
        for (int t = 0; t < CH; t++) s += sKp[t * KPAD + tid];
        g_kps[blk * 16 + tid] = s;
    }

    // ---- pass 2: Gpart = Kp^T @ x_chunk, thread owns 4 e-columns ----
    uint64_t ga[8][4];
#pragma unroll
    for (int p2 = 0; p2 < 8; p2++)
#pragma unroll
        for (int c = 0; c < 4; c++) ga[p2][c] = 0ull;

    const float4* xp = (const float4*)(x + (size_t)row0 * E) + tid;

    for (int t0 = 0; t0 < CH; t0 += 4) {
        float4 v[4];
#pragma unroll
        for (int u = 0; u < 4; u++) v[u] = xp[(size_t)(t0 + u) * (E / 4)];
#pragma unroll
        for (int u = 0; u < 4; u++) {
            const ulonglong2* kr = (const ulonglong2*)(sKp + (t0 + u) * KPAD);
            ulonglong2 k0 = kr[0], k1 = kr[1], k2 = kr[2], k3 = kr[3];
            uint64_t kp[8] = {k0.x, k0.y, k1.x, k1.y, k2.x, k2.y, k3.x, k3.y};
            float xa[4] = {v[u].x, v[u].y, v[u].z, v[u].w};
#pragma unroll
            for (int c = 0; c < 4; c++) {
                uint64_t xc = pack2(xa[c], xa[c]);
#pragma unroll
                for (int p2 = 0; p2 < 8; p2++) fma2(ga[p2][c], kp[p2], xc);
            }
        }
    }

    float* dst = g_Gpart + (size_t)blk * F * E + tid * 4;
#pragma unroll
    for (int p2 = 0; p2 < 8; p2++) {
        float2 u0 = unpack2(ga[p2][0]);
        float2 u1 = unpack2(ga[p2][1]);
        float2 u2 = unpack2(ga[p2][2]);
        float2 u3 = unpack2(ga[p2][3]);
        ((float4*)(dst + (size_t)(2 * p2) * E))[0]     = make_float4(u0.x, u1.x, u2.x, u3.x);
        ((float4*)(dst + (size_t)(2 * p2 + 1) * E))[0] = make_float4(u0.y, u1.y, u2.y, u3.y);
    }
}

// ============================================================
// k_red: reduce Gpart over 64 chunk-partials -> G. 256 blocks x 256 thr.
// ============================================================
__global__ void __launch_bounds__(256) k_red() {
    int idx = blockIdx.x * 256 + threadIdx.x;  // < 65536
    int b = idx >> 14;
    int rest = idx & 16383;  // f*1024 + e
    const float* src = g_Gpart + (size_t)b * SPB * (F * E) + rest;
    float s0 = 0.f, s1 = 0.f, s2 = 0.f, s3 = 0.f;
#pragma unroll 4
    for (int sp = 0; sp < SPB; sp += 4) {
        s0 += src[(size_t)(sp + 0) * (F * E)];
        s1 += src[(size_t)(sp + 1) * (F * E)];
        s2 += src[(size_t)(sp + 2) * (F * E)];
        s3 += src[(size_t)(sp + 3) * (F * E)];
    }
    g_G[idx] = ((s0 + s1) + (s2 + s3));
}

// ============================================================
// k_s2: S[b,f,:] = G[b,f,:] @ Wv + kpsum * bv.  grid (16,4), 128 thr.
// ============================================================
__global__ void __launch_bounds__(128) k_s2(const float* __restrict__ Wv,
                                            const float* __restrict__ bv) {
    int f = blockIdx.x;
    int b = blockIdx.y;
    int tid = threadIdx.x;
    __shared__ __align__(16) float sG[E];
    __shared__ float skr[64];
    __shared__ float s2[64];

    const float4* gsrc = (const float4*)(g_G + ((size_t)b * F + f) * E);
    ((float4*)sG)[tid] = gsrc[tid];
    ((float4*)sG)[tid + 128] = gsrc[tid + 128];
    if (tid < 64) skr[tid] = g_kps[(b * SPB + tid) * 16 + f];
    __syncthreads();

    int d = tid & 63, h = tid >> 6;
    float acc = 0.0f;
    const float* gp = sG + h * 512;
    const float* wp = Wv + (size_t)h * 512 * D + d;
#pragma unroll 8
    for (int e = 0; e < 512; e++) acc += gp[e] * wp[(size_t)e * D];

    if (h == 1) s2[d] = acc;
    __syncthreads();
    if (h == 0) {
        float kpsum = 0.0f;
        for (int i = 0; i < 64; i++) kpsum += skr[i];
        g_S[((size_t)b * F + f) * D + d] = acc + s2[d] + kpsum * bv[d];
    }
}

// ============================================================
// k_y: y = qP @ S.  128 blocks x 256 thr; thread = (tok-lane, d-half), 2 tokens.
// ============================================================
__global__ void __launch_bounds__(256) k_y(float* __restrict__ y) {
    __shared__ __align__(16) float sS[F * D];  // 4 KB
    int tid = threadIdx.x;
    int bid = blockIdx.x;         // 256 tokens per block
    int b = bid >> 5;             // 32 blocks per batch
    const float4* ssrc = (const float4*)(g_S + (size_t)b * F * D);
    ((float4*)sS)[tid] = ssrc[tid];
    __syncthreads();

    int tl = tid & 127, g = tid >> 7;
    int t0 = bid * 256 + tl;
    int t1 = t0 + 128;

    const float4* qa = (const float4*)(g_qP + (size_t)t0 * F);
    const float4* qb = (const float4*)(g_qP + (size_t)t1 * F);
    float4 a0 = qa[0], a1 = qa[1], a2 = qa[2], a3 = qa[3];
    float4 b0 = qb[0], b1 = qb[1], b2 = qb[2], b3 = qb[3];
    float qva[16] = {a0.x, a0.y, a0.z, a0.w, a1.x, a1.y, a1.z, a1.w,
                     a2.x, a2.y, a2.z, a2.w, a3.x, a3.y, a3.z, a3.w};
    float qvb[16] = {b0.x, b0.y, b0.z, b0.w, b1.x, b1.y, b1.z, b1.w,
                     b2.x, b2.y, b2.z, b2.w, b3.x, b3.y, b3.z, b3.w};

    uint64_t accA[16], accB[16];  // 32 d-outputs each token
#pragma unroll
    for (int p = 0; p < 16; p++) { accA[p] = 0ull; accB[p] = 0ull; }

#pragma unroll
    for (int f = 0; f < F; f++) {
        const ulonglong2* sr = (const ulonglong2*)(sS + f * D + g * 32);  // broadcast
        uint64_t qfa = pack2(qva[f], qva[f]);
        uint64_t qfb = pack2(qvb[f], qvb[f]);
#pragma unroll
        for (int p = 0; p < 8; p++) {
            ulonglong2 w = sr[p];
            fma2(accA[2 * p],     qfa, w.x);
            fma2(accA[2 * p + 1], qfa, w.y);
            fma2(accB[2 * p],     qfb, w.x);
            fma2(accB[2 * p + 1], qfb, w.y);
        }
    }

    float4* dA = (float4*)(y + (size_t)t0 * D + g * 32);
    float4* dB = (float4*)(y + (size_t)t1 * D + g * 32);
#pragma unroll
    for (int p = 0; p < 8; p++) {
        float2 lo = unpack2(accA[2 * p]);
        float2 hi = unpack2(accA[2 * p + 1]);
        dA[p] = make_float4(lo.x, lo.y, hi.x, hi.y);
        lo = unpack2(accB[2 * p]);
        hi = unpack2(accB[2 * p + 1]);
        dB[p] = make_float4(lo.x, lo.y, hi.x, hi.y);
    }
}

// ============================================================
extern "C" void kernel_launch(void* const* d_in, const int* in_sizes, int n_in,
                              void* d_out, int out_size) {
    const float* x  = (const float*)d_in[0];
    const float* w  = (const float*)d_in[1];
    const float* Wq = (const float*)d_in[2];
    const float* bq = (const float*)d_in[3];
    const float* Wk = (const float*)d_in[4];
    const float* bk = (const float*)d_in[5];
    const float* Wv = (const float*)d_in[6];
    const float* bv = (const float*)d_in[7];
    float* y = (float*)d_out;

    cudaFuncSetAttribute(k_fused, cudaFuncAttributeMaxDynamicSharedMemorySize,
                         SMEM_FLOATS * 4);

    k_fold<<<64, 256>>>(Wq, bq, Wk, bk, w);
    k_fused<<<NBLK, 256, SMEM_FLOATS * 4>>>(x);
    k_red<<<256, 256>>>();
    dim3 gs(16, 4);
    k_s2<<<gs, 128>>>(Wv, bv);
    k_y<<<128, 256>>>(y);
}

// round 7
// speedup vs baseline: 2.4152x; 1.0731x over previous
#include <cuda_runtime.h>
#include <cstdint>

// Problem constants
#define B   4
#define T   8192
#define BT  32768     // B*T
#define E   1024      // n_embd
#define D   64        // d_head
#define M   8         // M_FEAT
#define F   16        // 2*M feature dim
#define CH  128       // tokens per fused block
#define NBLK (BT/CH)  // 256 blocks
#define SPB (T/CH)    // 64 chunks per batch
#define KPAD 20       // sKp row stride

// -------- scratch (device globals; no allocation) --------
__device__ __align__(16) float g_Wf[E * F];
__device__ __align__(16) float g_bf[F];
__device__ __align__(16) float g_qP[(size_t)BT * F];
__device__ __align__(16) float g_Gpart[(size_t)NBLK * F * E]; // 16 MB
__device__ __align__(16) float g_Spart[16 * B * F * D];       // e-split S partials
__device__ __align__(16) float g_kps[NBLK * F];
__device__ __align__(16) float g_S[B * F * D];

// -------- packed f32x2 helpers --------
__device__ __forceinline__ uint64_t pack2(float lo, float hi) {
    uint64_t r;
    asm("mov.b64 %0, {%1, %2};" : "=l"(r) : "f"(lo), "f"(hi));
    return r;
}
__device__ __forceinline__ float2 unpack2(uint64_t v) {
    float2 r;
    asm("mov.b64 {%0, %1}, %2;" : "=f"(r.x), "=f"(r.y) : "l"(v));
    return r;
}
__device__ __forceinline__ void fma2(uint64_t& d, uint64_t a, uint64_t b) {
    asm("fma.rn.f32x2 %0, %1, %2, %0;" : "+l"(d) : "l"(a), "l"(b));
}

// ============================================================
// Kernel 0: fold weights
// ============================================================
__global__ void k_fold(const float* __restrict__ Wq, const float* __restrict__ bq,
                       const float* __restrict__ Wk, const float* __restrict__ bk,
                       const float* __restrict__ w) {
    int idx = blockIdx.x * blockDim.x + threadIdx.x;
    if (idx < E * F) {
        int j = idx & 15;
        int k = idx >> 4;
        const float* W = (j < 8) ? Wq : Wk;
        int jm = j & 7;
        float s = 0.0f;
#pragma unroll 8
        for (int d = 0; d < D; d++) s += W[k * D + d] * w[d * M + jm];
        g_Wf[k * F + j] = s;
    }
    if (blockIdx.x == 0 && idx < F) {
        int jm = idx & 7;
        const float* bb = (idx < 8) ? bq : bk;
        float s = 0.0f;
#pragma unroll 8
        for (int d = 0; d < D; d++) s += bb[d] * w[d * M + jm];
        g_bf[idx] = s;
    }
}

// ============================================================
// Fused kernel, double-buffered pass-1 staging.
// smem: [0..16383] sPart alias; buffers at 0 and 4736 (sX 4224 + sW 512);
//       sKp [128][KPAD]; sbf[16]
// ============================================================
#define SMEM_FLOATS (16384 + CH * KPAD + 16)

__global__ void __launch_bounds__(256, 2) k_fused(const float* __restrict__ x) {
    extern __shared__ __align__(16) float smem[];
    float* sPart = smem;
    float* sKp   = smem + 16384;
    float* sbf   = smem + 16384 + CH * KPAD;

    int tid = threadIdx.x;
    int blk = blockIdx.x;
    int row0 = blk * CH;
    int tg = tid & 31;
    int h  = tid >> 5;

    if (tid < 16) sbf[tid] = g_bf[tid];

    uint64_t acc[4][8];
#pragma unroll
    for (int u = 0; u < 4; u++)
#pragma unroll
        for (int q = 0; q < 8; q++) acc[u][q] = 0ull;

    const float4* xg = (const float4*)x;

    int t_[4], c4_[4];
#pragma unroll
    for (int q = 0; q < 4; q++) { int idx = q * 256 + tid; t_[q] = idx >> 3; c4_[q] = idx & 7; }

    float4 pre[4];
    float4 wpre = make_float4(0.f, 0.f, 0.f, 0.f);

    // prefetch + store chunk 0 into buf0
#pragma unroll
    for (int q = 0; q < 4; q++)
        pre[q] = xg[(size_t)(row0 + t_[q]) * (E / 4) + c4_[q]];
    if (tid < 128) wpre = ((const float4*)g_Wf)[tid];
    {
        float* sX = smem;
        float* sW = smem + 4224;
#pragma unroll
        for (int q = 0; q < 4; q++) {
            sX[(c4_[q] * 4 + 0) * 132 + t_[q]] = pre[q].x;
            sX[(c4_[q] * 4 + 1) * 132 + t_[q]] = pre[q].y;
            sX[(c4_[q] * 4 + 2) * 132 + t_[q]] = pre[q].z;
            sX[(c4_[q] * 4 + 3) * 132 + t_[q]] = pre[q].w;
        }
        if (tid < 128) ((float4*)sW)[tid] = wpre;
    }
    __syncthreads();

    for (int ch = 0; ch < 32; ch++) {
        int cur = ch & 1;
        float* sX = smem + cur * 4736;
        float* sW = sX + 4224;
        if (ch < 31) {
#pragma unroll
            for (int q = 0; q < 4; q++)
                pre[q] = xg[(size_t)(row0 + t_[q]) * (E / 4) + (ch + 1) * 8 + c4_[q]];
            if (tid < 128) wpre = ((const float4*)g_Wf)[(ch + 1) * 128 + tid];
        }
#pragma unroll
        for (int c = 0; c < 4; c++) {
            int k = 4 * h + c;
            float4 xv = *(const float4*)(sX + k * 132 + 4 * tg);
            const ulonglong2* wr = (const ulonglong2*)(sW + k * 16);
            ulonglong2 w0 = wr[0], w1 = wr[1], w2 = wr[2], w3 = wr[3];
            uint64_t wv[8] = {w0.x, w0.y, w1.x, w1.y, w2.x, w2.y, w3.x, w3.y};
            float xa[4] = {xv.x, xv.y, xv.z, xv.w};
#pragma unroll
            for (int u = 0; u < 4; u++) {
                uint64_t xx = pack2(xa[u], xa[u]);
#pragma unroll
                for (int q = 0; q < 8; q++) fma2(acc[u][q], wv[q], xx);
            }
        }
        if (ch < 31) {
            float* dX = smem + (1 - cur) * 4736;
            float* dW = dX + 4224;
#pragma unroll
            for (int q = 0; q < 4; q++) {
                dX[(c4_[q] * 4 + 0) * 132 + t_[q]] = pre[q].x;
                dX[(c4_[q] * 4 + 1) * 132 + t_[q]] = pre[q].y;
                dX[(c4_[q] * 4 + 2) * 132 + t_[q]] = pre[q].z;
                dX[(c4_[q] * 4 + 3) * 132 + t_[q]] = pre[q].w;
            }
            if (tid < 128) ((float4*)dW)[tid] = wpre;
        }
        __syncthreads();
    }

    // ---- write k-split partials: sPart[h][f][tok] ----
#pragma unroll
    for (int q = 0; q < 8; q++) {
        float2 v0 = unpack2(acc[0][q]);
        float2 v1 = unpack2(acc[1][q]);
        float2 v2 = unpack2(acc[2][q]);
        float2 v3 = unpack2(acc[3][q]);
        *(float4*)(sPart + h * 2048 + (2 * q) * 128 + 4 * tg)     = make_float4(v0.x, v1.x, v2.x, v3.x);
        *(float4*)(sPart + h * 2048 + (2 * q + 1) * 128 + 4 * tg) = make_float4(v0.y, v1.y, v2.y, v3.y);
    }
    __syncthreads();

    // ---- combine + sincos ----
    {
        int tok = tid & 127;
        int g = tid >> 7;
        float p[8];
#pragma unroll
        for (int j = 0; j < 8; j++) {
            int f = 8 * g + j;
            float s = 0.0f;
#pragma unroll
            for (int h2 = 0; h2 < 8; h2++) s += sPart[h2 * 2048 + f * 128 + tok];
            p[j] = s + sbf[f];
        }
        const float inv = 0.35355339059327376f;
        float cv[8], sv[8];
#pragma unroll
        for (int j = 0; j < 8; j++) {
            float s, c;
            __sincosf(p[j], &s, &c);
            cv[j] = c * inv; sv[j] = s * inv;
        }
        if (g == 0) {
            float4* qd = (float4*)(g_qP + (size_t)(row0 + tok) * F);
            qd[0] = make_float4(cv[0], cv[1], cv[2], cv[3]);
            qd[1] = make_float4(cv[4], cv[5], cv[6], cv[7]);
            qd[2] = make_float4(sv[0], sv[1], sv[2], sv[3]);
            qd[3] = make_float4(sv[4], sv[5], sv[6], sv[7]);
        } else {
            float4* kd = (float4*)(sKp + tok * KPAD);
            kd[0] = make_float4(cv[0], cv[1], cv[2], cv[3]);
            kd[1] = make_float4(cv[4], cv[5], cv[6], cv[7]);
            kd[2] = make_float4(sv[0], sv[1], sv[2], sv[3]);
            kd[3] = make_float4(sv[4], sv[5], sv[6], sv[7]);
        }
    }
    __syncthreads();

    // kpsum partial
    if (tid < 16) {
        float s = 0.0f;
        for (int t = 0; t < CH; t++) s += sKp[t * KPAD + tid];
        g_kps[blk * 16 + tid] = s;
    }

    // ---- pass 2: Gpart = Kp^T @ x_chunk ----
    uint64_t ga[8][4];
#pragma unroll
    for (int p2 = 0; p2 < 8; p2++)
#pragma unroll
        for (int c = 0; c < 4; c++) ga[p2][c] = 0ull;

    const float4* xp = (const float4*)(x + (size_t)row0 * E) + tid;

    for (int t0 = 0; t0 < CH; t0 += 4) {
        float4 v[4];
#pragma unroll
        for (int u = 0; u < 4; u++) v[u] = xp[(size_t)(t0 + u) * (E / 4)];
#pragma unroll
        for (int u = 0; u < 4; u++) {
            const ulonglong2* kr = (const ulonglong2*)(sKp + (t0 + u) * KPAD);
            ulonglong2 k0 = kr[0], k1 = kr[1], k2 = kr[2], k3 = kr[3];
            uint64_t kp[8] = {k0.x, k0.y, k1.x, k1.y, k2.x, k2.y, k3.x, k3.y};
            float xa[4] = {v[u].x, v[u].y, v[u].z, v[u].w};
#pragma unroll
            for (int c = 0; c < 4; c++) {
                uint64_t xc = pack2(xa[c], xa[c]);
#pragma unroll
                for (int p2 = 0; p2 < 8; p2++) fma2(ga[p2][c], kp[p2], xc);
            }
        }
    }

    float* dst = g_Gpart + (size_t)blk * F * E + tid * 4;
#pragma unroll
    for (int p2 = 0; p2 < 8; p2++) {
        float2 u0 = unpack2(ga[p2][0]);
        float2 u1 = unpack2(ga[p2][1]);
        float2 u2 = unpack2(ga[p2][2]);
        float2 u3 = unpack2(ga[p2][3]);
        ((float4*)(dst + (size_t)(2 * p2) * E))[0]     = make_float4(u0.x, u1.x, u2.x, u3.x);
        ((float4*)(dst + (size_t)(2 * p2 + 1) * E))[0] = make_float4(u0.y, u1.y, u2.y, u3.y);
    }
}

// ============================================================
// k_sp: per (es,b): reduce Gpart over sp for e-slice [es*64,+64),
//       then Spart = Gslice @ Wv_slice.  grid (16,4), 128 thr.
// ============================================================
__global__ void __launch_bounds__(128) k_sp(const float* __restrict__ Wv) {
    int es = blockIdx.x;
    int b  = blockIdx.y;
    int e0 = es * 64;
    int tid = threadIdx.x;
    __shared__ __align__(16) float sG[16][68];   // padded (2-way bcast conflict ok)
    __shared__ __align__(16) float sWv[64][64];

    int f  = tid >> 3;
    int eo = (tid & 7) * 8;

    // stage 1: reduce over 64 sp chunks, MLP-16 via sp-unroll 8
    float4 a0 = make_float4(0.f, 0.f, 0.f, 0.f);
    float4 a1 = make_float4(0.f, 0.f, 0.f, 0.f);
    const float* base = g_Gpart + (size_t)(b * SPB) * (F * E) + (size_t)f * E + e0 + eo;
#pragma unroll 8
    for (int sp = 0; sp < SPB; sp++) {
        const float4* p = (const float4*)(base + (size_t)sp * (F * E));
        float4 v0 = p[0], v1 = p[1];
        a0.x += v0.x; a0.y += v0.y; a0.z += v0.z; a0.w += v0.w;
        a1.x += v1.x; a1.y += v1.y; a1.z += v1.z; a1.w += v1.w;
    }
    *(float4*)&sG[f][eo]     = a0;
    *(float4*)&sG[f][eo + 4] = a1;

    // stage 2: stage Wv slice [64 e][64 d] into smem
    const float4* wsrc = (const float4*)(Wv + (size_t)e0 * D);
    for (int i = tid; i < 64 * 16; i += 128)
        ((float4*)sWv)[i] = wsrc[i];
    __syncthreads();

    // stage 3: Spart[f][dg..dg+8) = sum_e sG[f][e] * sWv[e][dg..]
    int dg = (tid & 7) * 8;
    float ac[8] = {0.f, 0.f, 0.f, 0.f, 0.f, 0.f, 0.f, 0.f};
#pragma unroll 4
    for (int e = 0; e < 64; e++) {
        float g = sG[f][e];
        float4 w0 = *(const float4*)&sWv[e][dg];
        float4 w1 = *(const float4*)&sWv[e][dg + 4];
        ac[0] += g * w0.x; ac[1] += g * w0.y; ac[2] += g * w0.z; ac[3] += g * w0.w;
        ac[4] += g * w1.x; ac[5] += g * w1.y; ac[6] += g * w1.z; ac[7] += g * w1.w;
    }
    float* dst = g_Spart + ((size_t)es * B + b) * (F * D) + f * D + dg;
    *(float4*)dst       = make_float4(ac[0], ac[1], ac[2], ac[3]);
    *(float4*)(dst + 4) = make_float4(ac[4], ac[5], ac[6], ac[7]);
}

// ============================================================
// k_sred: S = sum_es Spart + kpsum*bv.  16 blocks x 256 thr.
// ============================================================
__global__ void __launch_bounds__(256) k_sred(const float* __restrict__ bv) {
    int idx = blockIdx.x * 256 + threadIdx.x;  // < 4096
    int b = idx >> 10;
    int fd = idx & 1023;
    int f = fd >> 6;
    int d = fd & 63;
    float s = 0.0f;
#pragma unroll
    for (int es = 0; es < 16; es++)
        s += g_Spart[((size_t)es * B + b) * (F * D) + fd];
    float kp = 0.0f;
#pragma unroll 8
    for (int sp = 0; sp < SPB; sp++)
        kp += g_kps[(b * SPB + sp) * 16 + f];
    g_S[idx] = s + kp * bv[d];
}

// ============================================================
// k_y: y = qP @ S.  256 blocks x 256 thr; thread = (tok-lane, d-half).
// ============================================================
__global__ void __launch_bounds__(256) k_y(float* __restrict__ y) {
    __shared__ __align__(16) float sS[F * D];
    int tid = threadIdx.x;
    int bid = blockIdx.x;         // 128 tokens per block
    int b = bid >> 6;             // 64 blocks per batch
    ((float4*)sS)[tid] = ((const float4*)(g_S + (size_t)b * F * D))[tid];
    __syncthreads();

    int tl = tid & 127, g = tid >> 7;
    int t0 = bid * 128 + tl;

    const float4* qa = (const float4*)(g_qP + (size_t)t0 * F);
    float4 a0 = qa[0], a1 = qa[1], a2 = qa[2], a3 = qa[3];
    float qv[16] = {a0.x, a0.y, a0.z, a0.w, a1.x, a1.y, a1.z, a1.w,
                    a2.x, a2.y, a2.z, a2.w, a3.x, a3.y, a3.z, a3.w};

    uint64_t acc[16];
#pragma unroll
    for (int p = 0; p < 16; p++) acc[p] = 0ull;

#pragma unroll
    for (int f = 0; f < F; f++) {
        const ulonglong2* sr = (const ulonglong2*)(sS + f * D + g * 32);
        uint64_t qf = pack2(qv[f], qv[f]);
#pragma unroll
        for (int p = 0; p < 8; p++) {
            ulonglong2 w = sr[p];
            fma2(acc[2 * p],     qf, w.x);
            fma2(acc[2 * p + 1], qf, w.y);
        }
    }

    float4* dA = (float4*)(y + (size_t)t0 * D + g * 32);
#pragma unroll
    for (int p = 0; p < 8; p++) {
        float2 lo = unpack2(acc[2 * p]);
        float2 hi = unpack2(acc[2 * p + 1]);
        dA[p] = make_float4(lo.x, lo.y, hi.x, hi.y);
    }
}

// ============================================================
extern "C" void kernel_launch(void* const* d_in, const int* in_sizes, int n_in,
                              void* d_out, int out_size) {
    const float* x  = (const float*)d_in[0];
    const float* w  = (const float*)d_in[1];
    const float* Wq = (const float*)d_in[2];
    const float* bq = (const float*)d_in[3];
    const float* Wk = (const float*)d_in[4];
    const float* bk = (const float*)d_in[5];
    const float* Wv = (const float*)d_in[6];
    const float* bv = (const float*)d_in[7];
    float* y = (float*)d_out;

    cudaFuncSetAttribute(k_fused, cudaFuncAttributeMaxDynamicSharedMemorySize,
                         SMEM_FLOATS * 4);

    k_fold<<<64, 256>>>(Wq, bq, Wk, bk, w);
    k_fused<<<NBLK, 256, SMEM_FLOATS * 4>>>(x);
    dim3 gsp(16, 4);
    k_sp<<<gsp, 128>>>(Wv);
    k_sred<<<16, 256>>>(bv);
    k_y<<<256, 256>>>(y);
}

// round 8
// speedup vs baseline: 2.6990x; 1.1175x over previous
#include <cuda_runtime.h>
#include <cstdint>

// Problem constants
#define B   4
#define T   8192
#define BT  32768     // B*T
#define E   1024      // n_embd
#define D   64        // d_head
#define M   8         // M_FEAT
#define F   16        // 2*M feature dim
#define CH  128       // tokens per fused block
#define NBLK (BT/CH)  // 256 blocks
#define SPB (T/CH)    // 64 chunks per batch
#define KPAD 20       // sKp row stride
#define XS  33        // sX row stride (odd -> conflict-free scalar access)
#define PPAD 20       // sPart row stride
#define BUF 4736      // per-buffer floats: sX 128*33=4224 + sW 512
#define NSL 32        // S partial slices (16 es x 2 spg)

// -------- scratch (device globals; no allocation) --------
__device__ __align__(16) float g_Wf[E * F];
__device__ __align__(16) float g_bf[F];
__device__ __align__(16) float g_qP[(size_t)BT * F];
__device__ __align__(16) float g_Gpart[(size_t)NBLK * F * E]; // 16 MB
__device__ __align__(16) float g_Spart[NSL * B * F * D];      // 512 KB
__device__ __align__(16) float g_kps[F * NBLK];               // transposed [f][blk]
__device__ __align__(16) float g_S_unused[4];                 // (kept tiny)

// -------- packed f32x2 helpers --------
__device__ __forceinline__ uint64_t pack2(float lo, float hi) {
    uint64_t r;
    asm("mov.b64 %0, {%1, %2};" : "=l"(r) : "f"(lo), "f"(hi));
    return r;
}
__device__ __forceinline__ float2 unpack2(uint64_t v) {
    float2 r;
    asm("mov.b64 {%0, %1}, %2;" : "=f"(r.x), "=f"(r.y) : "l"(v));
    return r;
}
__device__ __forceinline__ void fma2(uint64_t& d, uint64_t a, uint64_t b) {
    asm("fma.rn.f32x2 %0, %1, %2, %0;" : "+l"(d) : "l"(a), "l"(b));
}

// ============================================================
// Kernel 0: fold weights  Wf = [Wq@w | Wk@w], bf = [bq@w | bk@w]
// ============================================================
__global__ void k_fold(const float* __restrict__ Wq, const float* __restrict__ bq,
                       const float* __restrict__ Wk, const float* __restrict__ bk,
                       const float* __restrict__ w) {
    __shared__ float sw[D * M];  // 512
    int t = threadIdx.x;
    sw[t] = w[t];
    sw[t + 256] = w[t + 256];
    __syncthreads();

    int idx = blockIdx.x * blockDim.x + t;  // 0 .. 16383
    if (idx < E * F) {
        int j = idx & 15;
        int k = idx >> 4;
        const float* W = (j < 8) ? Wq : Wk;
        int jm = j & 7;
        const float4* Wr = (const float4*)(W + (size_t)k * D);
        float s = 0.0f;
#pragma unroll
        for (int d4 = 0; d4 < 16; d4++) {
            float4 wv = Wr[d4];
            s += wv.x * sw[(d4 * 4 + 0) * M + jm];
            s += wv.y * sw[(d4 * 4 + 1) * M + jm];
            s += wv.z * sw[(d4 * 4 + 2) * M + jm];
            s += wv.w * sw[(d4 * 4 + 3) * M + jm];
        }
        g_Wf[k * F + j] = s;
    }
    if (blockIdx.x == 0 && idx < F) {
        int jm = idx & 7;
        const float* bb = (idx < 8) ? bq : bk;
        float s = 0.0f;
#pragma unroll 8
        for (int d = 0; d < D; d++) s += bb[d] * sw[d * M + jm];
        g_bf[idx] = s;
    }
}

// ============================================================
// Fused kernel. smem (floats):
//   [0 .. 20479]  sPart [8][128][PPAD]; double buffers alias at 0 and BUF
//                 (buf = sX[128][XS] + sW[32][16])
//   [20480 ..]    sKp [128][KPAD]
//   [23040 ..]    sbf [16]
// pass1: thread (tg,h): tokens {tg+32u}, cols {4h..4h+3} per 32-col chunk
// ============================================================
#define SMEM_FLOATS (20480 + CH * KPAD + 16)

__global__ void __launch_bounds__(256, 2) k_fused(const float* __restrict__ x) {
    extern __shared__ __align__(16) float smem[];
    float* sPart = smem;
    float* sKp   = smem + 20480;
    float* sbf   = smem + 20480 + CH * KPAD;

    int tid = threadIdx.x;
    int blk = blockIdx.x;
    int row0 = blk * CH;
    int tg = tid & 31;
    int h  = tid >> 5;

    if (tid < 16) sbf[tid] = g_bf[tid];

    uint64_t acc[4][8];
#pragma unroll
    for (int u = 0; u < 4; u++)
#pragma unroll
        for (int q = 0; q < 8; q++) acc[u][q] = 0ull;

    const float4* xg = (const float4*)x;

    int t_[4], c4_[4];
#pragma unroll
    for (int q = 0; q < 4; q++) { int idx = q * 256 + tid; t_[q] = idx >> 3; c4_[q] = idx & 7; }

    float4 pre[4];
    float4 wpre = make_float4(0.f, 0.f, 0.f, 0.f);

    // prefetch + store chunk 0 into buf0
#pragma unroll
    for (int q = 0; q < 4; q++)
        pre[q] = xg[(size_t)(row0 + t_[q]) * (E / 4) + c4_[q]];
    if (tid < 128) wpre = ((const float4*)g_Wf)[tid];
    {
        float* sX = smem;
        float* sW = smem + 4224;
#pragma unroll
        for (int q = 0; q < 4; q++) {
            int base = t_[q] * XS + c4_[q] * 4;
            sX[base + 0] = pre[q].x;
            sX[base + 1] = pre[q].y;
            sX[base + 2] = pre[q].z;
            sX[base + 3] = pre[q].w;
        }
        if (tid < 128) ((float4*)sW)[tid] = wpre;
    }
    __syncthreads();

    for (int ch = 0; ch < 32; ch++) {
        int cur = ch & 1;
        float* sX = smem + cur * BUF;
        float* sW = sX + 4224;
        if (ch < 31) {
#pragma unroll
            for (int q = 0; q < 4; q++)
                pre[q] = xg[(size_t)(row0 + t_[q]) * (E / 4) + (ch + 1) * 8 + c4_[q]];
            if (tid < 128) wpre = ((const float4*)g_Wf)[(ch + 1) * 128 + tid];
        }
#pragma unroll
        for (int c = 0; c < 4; c++) {
            int kl = 4 * h + c;
            const ulonglong2* wr = (const ulonglong2*)(sW + kl * 16);
            ulonglong2 w0 = wr[0], w1 = wr[1], w2 = wr[2], w3 = wr[3];
            uint64_t wv[8] = {w0.x, w0.y, w1.x, w1.y, w2.x, w2.y, w3.x, w3.y};
#pragma unroll
            for (int u = 0; u < 4; u++) {
                float xv = sX[(tg + 32 * u) * XS + kl];
                uint64_t xx = pack2(xv, xv);
#pragma unroll
                for (int q = 0; q < 8; q++) fma2(acc[u][q], wv[q], xx);
            }
        }
        if (ch < 31) {
            float* dX = smem + (1 - cur) * BUF;
            float* dW = dX + 4224;
#pragma unroll
            for (int q = 0; q < 4; q++) {
                int base = t_[q] * XS + c4_[q] * 4;
                dX[base + 0] = pre[q].x;
                dX[base + 1] = pre[q].y;
                dX[base + 2] = pre[q].z;
                dX[base + 3] = pre[q].w;
            }
            if (tid < 128) ((float4*)dW)[tid] = wpre;
        }
        __syncthreads();
    }

    // ---- write h-split partials: sPart[h][tok][f], conflict-free float4 ----
#pragma unroll
    for (int u = 0; u < 4; u++) {
        int tok = tg + 32 * u;
        float* dp = sPart + h * 2560 + tok * PPAD;
        float2 a0 = unpack2(acc[u][0]);
        float2 a1 = unpack2(acc[u][1]);
        float2 a2 = unpack2(acc[u][2]);
        float2 a3 = unpack2(acc[u][3]);
        float2 a4 = unpack2(acc[u][4]);
        float2 a5 = unpack2(acc[u][5]);
        float2 a6 = unpack2(acc[u][6]);
        float2 a7 = unpack2(acc[u][7]);
        *(float4*)(dp + 0)  = make_float4(a0.x, a0.y, a1.x, a1.y);
        *(float4*)(dp + 4)  = make_float4(a2.x, a2.y, a3.x, a3.y);
        *(float4*)(dp + 8)  = make_float4(a4.x, a4.y, a5.x, a5.y);
        *(float4*)(dp + 12) = make_float4(a6.x, a6.y, a7.x, a7.y);
    }
    __syncthreads();

    // ---- combine + sincos: thread (tok, g) handles 8 features ----
    {
        int tok = tid & 127;
        int g = tid >> 7;
        float4 P0 = make_float4(0.f, 0.f, 0.f, 0.f);
        float4 P1 = make_float4(0.f, 0.f, 0.f, 0.f);
#pragma unroll
        for (int h2 = 0; h2 < 8; h2++) {
            float4 v0 = *(const float4*)(sPart + h2 * 2560 + tok * PPAD + g * 8);
            float4 v1 = *(const float4*)(sPart + h2 * 2560 + tok * PPAD + g * 8 + 4);
            P0.x += v0.x; P0.y += v0.y; P0.z += v0.z; P0.w += v0.w;
            P1.x += v1.x; P1.y += v1.y; P1.z += v1.z; P1.w += v1.w;
        }
        float p[8] = {P0.x + sbf[8 * g + 0], P0.y + sbf[8 * g + 1],
                      P0.z + sbf[8 * g + 2], P0.w + sbf[8 * g + 3],
                      P1.x + sbf[8 * g + 4], P1.y + sbf[8 * g + 5],
                      P1.z + sbf[8 * g + 6], P1.w + sbf[8 * g + 7]};
        const float inv = 0.35355339059327376f;
        float cv[8], sv[8];
#pragma unroll
        for (int j = 0; j < 8; j++) {
            float s, c;
            __sincosf(p[j], &s, &c);
            cv[j] = c * inv; sv[j] = s * inv;
        }
        if (g == 0) {
            float4* qd = (float4*)(g_qP + (size_t)(row0 + tok) * F);
            qd[0] = make_float4(cv[0], cv[1], cv[2], cv[3]);
            qd[1] = make_float4(cv[4], cv[5], cv[6], cv[7]);
            qd[2] = make_float4(sv[0], sv[1], sv[2], sv[3]);
            qd[3] = make_float4(sv[4], sv[5], sv[6], sv[7]);
        } else {
            float4* kd = (float4*)(sKp + tok * KPAD);
            kd[0] = make_float4(cv[0], cv[1], cv[2], cv[3]);
            kd[1] = make_float4(cv[4], cv[5], cv[6], cv[7]);
            kd[2] = make_float4(sv[0], sv[1], sv[2], sv[3]);
            kd[3] = make_float4(sv[4], sv[5], sv[6], sv[7]);
        }
    }
    __syncthreads();

    // kpsum partial (deterministic), transposed layout
    if (tid < 16) {
        float s = 0.0f;
        for (int t = 0; t < CH; t++) s += sKp[t * KPAD + tid];
        g_kps[tid * NBLK + blk] = s;
    }

    // ---- pass 2: Gpart = Kp^T @ x_chunk, thread owns 4 e-columns ----
    uint64_t ga[8][4];
#pragma unroll
    for (int p2 = 0; p2 < 8; p2++)
#pragma unroll
        for (int c = 0; c < 4; c++) ga[p2][c] = 0ull;

    const float4* xp = (const float4*)(x + (size_t)row0 * E) + tid;

    for (int t0 = 0; t0 < CH; t0 += 4) {
        float4 v[4];
#pragma unroll
        for (int u = 0; u < 4; u++) v[u] = xp[(size_t)(t0 + u) * (E / 4)];
#pragma unroll
        for (int u = 0; u < 4; u++) {
            const ulonglong2* kr = (const ulonglong2*)(sKp + (t0 + u) * KPAD);
            ulonglong2 k0 = kr[0], k1 = kr[1], k2 = kr[2], k3 = kr[3];
            uint64_t kp[8] = {k0.x, k0.y, k1.x, k1.y, k2.x, k2.y, k3.x, k3.y};
            float xa[4] = {v[u].x, v[u].y, v[u].z, v[u].w};
#pragma unroll
            for (int c = 0; c < 4; c++) {
                uint64_t xc = pack2(xa[c], xa[c]);
#pragma unroll
                for (int p2 = 0; p2 < 8; p2++) fma2(ga[p2][c], kp[p2], xc);
            }
        }
    }

    float* dst = g_Gpart + (size_t)blk * F * E + tid * 4;
#pragma unroll
    for (int p2 = 0; p2 < 8; p2++) {
        float2 u0 = unpack2(ga[p2][0]);
        float2 u1 = unpack2(ga[p2][1]);
        float2 u2 = unpack2(ga[p2][2]);
        float2 u3 = unpack2(ga[p2][3]);
        ((float4*)(dst + (size_t)(2 * p2) * E))[0]     = make_float4(u0.x, u1.x, u2.x, u3.x);
        ((float4*)(dst + (size_t)(2 * p2 + 1) * E))[0] = make_float4(u0.y, u1.y, u2.y, u3.y);
    }
}

// ============================================================
// k_sp: per (es,b,spg): reduce Gpart over 32 sp chunks for e-slice
//       [es*64,+64), then Spart = Gslice @ Wv_slice.  grid (16,4,2).
// ============================================================
__global__ void __launch_bounds__(128) k_sp(const float* __restrict__ Wv) {
    int es  = blockIdx.x;
    int b   = blockIdx.y;
    int spg = blockIdx.z;
    int e0 = es * 64;
    int tid = threadIdx.x;
    __shared__ __align__(16) float sG[16][68];
    __shared__ __align__(16) float sWv[64][64];

    int f  = tid >> 3;
    int eo = (tid & 7) * 8;

    float4 a0 = make_float4(0.f, 0.f, 0.f, 0.f);
    float4 a1 = make_float4(0.f, 0.f, 0.f, 0.f);
    const float* base = g_Gpart + (size_t)(b * SPB + spg * 32) * (F * E) + (size_t)f * E + e0 + eo;
#pragma unroll 8
    for (int sp = 0; sp < 32; sp++) {
        const float4* p = (const float4*)(base + (size_t)sp * (F * E));
        float4 v0 = p[0], v1 = p[1];
        a0.x += v0.x; a0.y += v0.y; a0.z += v0.z; a0.w += v0.w;
        a1.x += v1.x; a1.y += v1.y; a1.z += v1.z; a1.w += v1.w;
    }
    *(float4*)&sG[f][eo]     = a0;
    *(float4*)&sG[f][eo + 4] = a1;

    const float4* wsrc = (const float4*)(Wv + (size_t)e0 * D);
    for (int i = tid; i < 64 * 16; i += 128)
        ((float4*)sWv)[i] = wsrc[i];
    __syncthreads();

    int dg = (tid & 7) * 8;
    float ac[8] = {0.f, 0.f, 0.f, 0.f, 0.f, 0.f, 0.f, 0.f};
#pragma unroll 4
    for (int e = 0; e < 64; e++) {
        float g = sG[f][e];
        float4 w0 = *(const float4*)&sWv[e][dg];
        float4 w1 = *(const float4*)&sWv[e][dg + 4];
        ac[0] += g * w0.x; ac[1] += g * w0.y; ac[2] += g * w0.z; ac[3] += g * w0.w;
        ac[4] += g * w1.x; ac[5] += g * w1.y; ac[6] += g * w1.z; ac[7] += g * w1.w;
    }
    float* dst = g_Spart + ((size_t)(spg * 16 + es) * B + b) * (F * D) + f * D + dg;
    *(float4*)dst       = make_float4(ac[0], ac[1], ac[2], ac[3]);
    *(float4*)(dst + 4) = make_float4(ac[4], ac[5], ac[6], ac[7]);
}

// ============================================================
// k_y: prologue builds S[b] in smem (Spart 32-slice sum + kpsum*bv),
//      then y = qP @ S.  256 blocks x 256 thr, 128 tokens/block.
// ============================================================
__global__ void __launch_bounds__(256) k_y(float* __restrict__ y,
                                           const float* __restrict__ bv) {
    __shared__ __align__(16) float sS[F * D];
    __shared__ float skp[16];
    __shared__ float sred[64];
    int tid = threadIdx.x;
    int bid = blockIdx.x;
    int b = bid >> 6;  // 64 blocks per batch

    // kpsum partials: 64 threads, f = t>>2, quarter = t&3
    if (tid < 64) {
        int f = tid >> 2, part = tid & 3;
        const float4* kp4 = (const float4*)(g_kps + f * NBLK + b * 64 + part * 16);
        float4 v0 = kp4[0], v1 = kp4[1], v2 = kp4[2], v3 = kp4[3];
        sred[tid] = ((v0.x + v0.y) + (v0.z + v0.w)) + ((v1.x + v1.y) + (v1.z + v1.w))
                  + ((v2.x + v2.y) + (v2.z + v2.w)) + ((v3.x + v3.y) + (v3.z + v3.w));
    }

    // Spart 32-slice sum: thread owns 4 fd (one float4)
    float4 a = make_float4(0.f, 0.f, 0.f, 0.f);
#pragma unroll 8
    for (int sl = 0; sl < NSL; sl++) {
        float4 v = ((const float4*)(g_Spart + ((size_t)sl * B + b) * (F * D)))[tid];
        a.x += v.x; a.y += v.y; a.z += v.z; a.w += v.w;
    }
    __syncthreads();
    if (tid < 16)
        skp[tid] = (sred[4 * tid] + sred[4 * tid + 1]) + (sred[4 * tid + 2] + sred[4 * tid + 3]);
    __syncthreads();

    {
        int f = tid >> 4;
        int d = (tid * 4) & 63;
        float kv = skp[f];
        float4 bvv = *(const float4*)(bv + d);
        ((float4*)sS)[tid] = make_float4(a.x + kv * bvv.x, a.y + kv * bvv.y,
                                         a.z + kv * bvv.z, a.w + kv * bvv.w);
    }
    __syncthreads();

    int tl = tid & 127, g = tid >> 7;
    int t0 = bid * 128 + tl;

    const float4* qa = (const float4*)(g_qP + (size_t)t0 * F);
    float4 a0 = qa[0], a1 = qa[1], a2 = qa[2], a3 = qa[3];
    float qv[16] = {a0.x, a0.y, a0.z, a0.w, a1.x, a1.y, a1.z, a1.w,
                    a2.x, a2.y, a2.z, a2.w, a3.x, a3.y, a3.z, a3.w};

    uint64_t acc[16];
#pragma unroll
    for (int p = 0; p < 16; p++) acc[p] = 0ull;

#pragma unroll
    for (int f = 0; f < F; f++) {
        const ulonglong2* sr = (const ulonglong2*)(sS + f * D + g * 32);
        uint64_t qf = pack2(qv[f], qv[f]);
#pragma unroll
        for (int p = 0; p < 8; p++) {
            ulonglong2 w = sr[p];
            fma2(acc[2 * p],     qf, w.x);
            fma2(acc[2 * p + 1], qf, w.y);
        }
    }

    float4* dA = (float4*)(y + (size_t)t0 * D + g * 32);
#pragma unroll
    for (int p = 0; p < 8; p++) {
        float2 lo = unpack2(acc[2 * p]);
        float2 hi = unpack2(acc[2 * p + 1]);
        dA[p] = make_float4(lo.x, lo.y, hi.x, hi.y);
    }
}

// ============================================================
extern "C" void kernel_launch(void* const* d_in, const int* in_sizes, int n_in,
                              void* d_out, int out_size) {
    const float* x  = (const float*)d_in[0];
    const float* w  = (const float*)d_in[1];
    const float* Wq = (const float*)d_in[2];
    const float* bq = (const float*)d_in[3];
    const float* Wk = (const float*)d_in[4];
    const float* bk = (const float*)d_in[5];
    const float* Wv = (const float*)d_in[6];
    const float* bv = (const float*)d_in[7];
    float* y = (float*)d_out;

    cudaFuncSetAttribute(k_fused, cudaFuncAttributeMaxDynamicSharedMemorySize,
                         SMEM_FLOATS * 4);

    k_fold<<<64, 256>>>(Wq, bq, Wk, bk, w);
    k_fused<<<NBLK, 256, SMEM_FLOATS * 4>>>(x);
    dim3 gsp(16, 4, 2);
    k_sp<<<gsp, 128>>>(Wv);
    k_y<<<256, 256>>>(y, bv);
}

// round 11
// speedup vs baseline: 2.7340x; 1.0130x over previous
#include <cuda_runtime.h>
#include <cstdint>

// Problem constants
#define B   4
#define T   8192
#define BT  32768     // B*T
#define E   1024      // n_embd
#define D   64        // d_head
#define M   8         // M_FEAT
#define F   16        // 2*M feature dim
#define CH  128       // tokens per fused block
#define NBLK (BT/CH)  // 256 blocks
#define SPB (T/CH)    // 64 chunks per batch
#define KPAD 20       // sKp row stride
#define XS  33        // sX row stride (odd -> conflict-free scalar access)
#define PPAD 20       // sPart row stride
#define BUF 4736      // per-buffer floats: sX 128*33=4224 + sW 512
#define NSL 32        // S partial slices (16 es x 2 spg)

// -------- scratch (device globals; no allocation) --------
__device__ __align__(16) float g_Wf[E * F];
__device__ __align__(16) float g_bf[F];
__device__ __align__(16) float g_qP[(size_t)BT * F];
__device__ __align__(16) float g_Gpart[(size_t)NBLK * F * E]; // 16 MB
__device__ __align__(16) float g_Spart[NSL * B * F * D];      // 512 KB
__device__ __align__(16) float g_kps[F * NBLK];               // transposed [f][blk]
__device__ __align__(16) float g_S_unused[4];                 // (kept tiny)

// -------- packed f32x2 helpers --------
__device__ __forceinline__ uint64_t pack2(float lo, float hi) {
    uint64_t r;
    asm("mov.b64 %0, {%1, %2};" : "=l"(r) : "f"(lo), "f"(hi));
    return r;
}
__device__ __forceinline__ float2 unpack2(uint64_t v) {
    float2 r;
    asm("mov.b64 {%0, %1}, %2;" : "=f"(r.x), "=f"(r.y) : "l"(v));
    return r;
}
__device__ __forceinline__ void fma2(uint64_t& d, uint64_t a, uint64_t b) {
    asm("fma.rn.f32x2 %0, %1, %2, %0;" : "+l"(d) : "l"(a), "l"(b));
}

// ============================================================
// Kernel 0: fold weights  Wf = [Wq@w | Wk@w], bf = [bq@w | bk@w]
// ============================================================
__global__ void k_fold(const float* __restrict__ Wq, const float* __restrict__ bq,
                       const float* __restrict__ Wk, const float* __restrict__ bk,
                       const float* __restrict__ w) {
    __shared__ float sw[D * M];  // 512
    int t = threadIdx.x;
    sw[t] = w[t];
    sw[t + 256] = w[t + 256];
    __syncthreads();

    int idx = blockIdx.x * blockDim.x + t;  // 0 .. 16383
    if (idx < E * F) {
        int j = idx & 15;
        int k = idx >> 4;
        const float* W = (j < 8) ? Wq : Wk;
        int jm = j & 7;
        const float4* Wr = (const float4*)(W + (size_t)k * D);
        float s = 0.0f;
#pragma unroll
        for (int d4 = 0; d4 < 16; d4++) {
            float4 wv = Wr[d4];
            s += wv.x * sw[(d4 * 4 + 0) * M + jm];
            s += wv.y * sw[(d4 * 4 + 1) * M + jm];
            s += wv.z * sw[(d4 * 4 + 2) * M + jm];
            s += wv.w * sw[(d4 * 4 + 3) * M + jm];
        }
        g_Wf[k * F + j] = s;
    }
    if (blockIdx.x == 0 && idx < F) {
        int jm = idx & 7;
        const float* bb = (idx < 8) ? bq : bk;
        float s = 0.0f;
#pragma unroll 8
        for (int d = 0; d < D; d++) s += bb[d] * sw[d * M + jm];
        g_bf[idx] = s;
    }
}

// ============================================================
// Fused kernel. smem (floats):
//   [0 .. 20479]  sPart [8][128][PPAD]; double buffers alias at 0 and BUF
//                 (buf = sX[128][XS] + sW[32][16])
//   [20480 ..]    sKp [128][KPAD]
//   [23040 ..]    sbf [16]
// pass1: thread (tg,h): tokens {tg+32u}, cols {4h..4h+3} per 32-col chunk
// ============================================================
#define SMEM_FLOATS (20480 + CH * KPAD + 16)

__global__ void __launch_bounds__(256, 2) k_fused(const float* __restrict__ x) {
    extern __shared__ __align__(16) float smem[];
    float* sPart = smem;
    float* sKp   = smem + 20480;
    float* sbf   = smem + 20480 + CH * KPAD;

    int tid = threadIdx.x;
    int blk = blockIdx.x;
    int row0 = blk * CH;
    int tg = tid & 31;
    int h  = tid >> 5;

    if (tid < 16) sbf[tid] = g_bf[tid];

    uint64_t acc[4][8];
#pragma unroll
    for (int u = 0; u < 4; u++)
#pragma unroll
        for (int q = 0; q < 8; q++) acc[u][q] = 0ull;

    const float4* xg = (const float4*)x;

    int t_[4], c4_[4];
#pragma unroll
    for (int q = 0; q < 4; q++) { int idx = q * 256 + tid; t_[q] = idx >> 3; c4_[q] = idx & 7; }

    float4 pre[4];
    float4 wpre = make_float4(0.f, 0.f, 0.f, 0.f);

    // prefetch + store chunk 0 into buf0
#pragma unroll
    for (int q = 0; q < 4; q++)
        pre[q] = xg[(size_t)(row0 + t_[q]) * (E / 4) + c4_[q]];
    if (tid < 128) wpre = ((const float4*)g_Wf)[tid];
    {
        float* sX = smem;
        float* sW = smem + 4224;
#pragma unroll
        for (int q = 0; q < 4; q++) {
            int base = t_[q] * XS + c4_[q] * 4;
            sX[base + 0] = pre[q].x;
            sX[base + 1] = pre[q].y;
            sX[base + 2] = pre[q].z;
            sX[base + 3] = pre[q].w;
        }
        if (tid < 128) ((float4*)sW)[tid] = wpre;
    }
    __syncthreads();

    for (int ch = 0; ch < 32; ch++) {
        int cur = ch & 1;
        float* sX = smem + cur * BUF;
        float* sW = sX + 4224;
        if (ch < 31) {
#pragma unroll
            for (int q = 0; q < 4; q++)
                pre[q] = xg[(size_t)(row0 + t_[q]) * (E / 4) + (ch + 1) * 8 + c4_[q]];
            if (tid < 128) wpre = ((const float4*)g_Wf)[(ch + 1) * 128 + tid];
        }
#pragma unroll
        for (int c = 0; c < 4; c++) {
            int kl = 4 * h + c;
            const ulonglong2* wr = (const ulonglong2*)(sW + kl * 16);
            ulonglong2 w0 = wr[0], w1 = wr[1], w2 = wr[2], w3 = wr[3];
            uint64_t wv[8] = {w0.x, w0.y, w1.x, w1.y, w2.x, w2.y, w3.x, w3.y};
#pragma unroll
            for (int u = 0; u < 4; u++) {
                float xv = sX[(tg + 32 * u) * XS + kl];
                uint64_t xx = pack2(xv, xv);
#pragma unroll
                for (int q = 0; q < 8; q++) fma2(acc[u][q], wv[q], xx);
            }
        }
        if (ch < 31) {
            float* dX = smem + (1 - cur) * BUF;
            float* dW = dX + 4224;
#pragma unroll
            for (int q = 0; q < 4; q++) {
                int base = t_[q] * XS + c4_[q] * 4;
                dX[base + 0] = pre[q].x;
                dX[base + 1] = pre[q].y;
                dX[base + 2] = pre[q].z;
                dX[base + 3] = pre[q].w;
            }
            if (tid < 128) ((float4*)dW)[tid] = wpre;
        }
        __syncthreads();
    }

    // ---- write h-split partials: sPart[h][tok][f], conflict-free float4 ----
#pragma unroll
    for (int u = 0; u < 4; u++) {
        int tok = tg + 32 * u;
        float* dp = sPart + h * 2560 + tok * PPAD;
        float2 a0 = unpack2(acc[u][0]);
        float2 a1 = unpack2(acc[u][1]);
        float2 a2 = unpack2(acc[u][2]);
        float2 a3 = unpack2(acc[u][3]);
        float2 a4 = unpack2(acc[u][4]);
        float2 a5 = unpack2(acc[u][5]);
        float2 a6 = unpack2(acc[u][6]);
        float2 a7 = unpack2(acc[u][7]);
        *(float4*)(dp + 0)  = make_float4(a0.x, a0.y, a1.x, a1.y);
        *(float4*)(dp + 4)  = make_float4(a2.x, a2.y, a3.x, a3.y);
        *(float4*)(dp + 8)  = make_float4(a4.x, a4.y, a5.x, a5.y);
        *(float4*)(dp + 12) = make_float4(a6.x, a6.y, a7.x, a7.y);
    }
    __syncthreads();

    // ---- combine + sincos: thread (tok, g) handles 8 features ----
    {
        int tok = tid & 127;
        int g = tid >> 7;
        float4 P0 = make_float4(0.f, 0.f, 0.f, 0.f);
        float4 P1 = make_float4(0.f, 0.f, 0.f, 0.f);
#pragma unroll
        for (int h2 = 0; h2 < 8; h2++) {
            float4 v0 = *(const float4*)(sPart + h2 * 2560 + tok * PPAD + g * 8);
            float4 v1 = *(const float4*)(sPart + h2 * 2560 + tok * PPAD + g * 8 + 4);
            P0.x += v0.x; P0.y += v0.y; P0.z += v0.z; P0.w += v0.w;
            P1.x += v1.x; P1.y += v1.y; P1.z += v1.z; P1.w += v1.w;
        }
        float p[8] = {P0.x + sbf[8 * g + 0], P0.y + sbf[8 * g + 1],
                      P0.z + sbf[8 * g + 2], P0.w + sbf[8 * g + 3],
                      P1.x + sbf[8 * g + 4], P1.y + sbf[8 * g + 5],
                      P1.z + sbf[8 * g + 6], P1.w + sbf[8 * g + 7]};
        const float inv = 0.35355339059327376f;
        float cv[8], sv[8];
#pragma unroll
        for (int j = 0; j < 8; j++) {
            float s, c;
            __sincosf(p[j], &s, &c);
            cv[j] = c * inv; sv[j] = s * inv;
        }
        if (g == 0) {
            float4* qd = (float4*)(g_qP + (size_t)(row0 + tok) * F);
            qd[0] = make_float4(cv[0], cv[1], cv[2], cv[3]);
            qd[1] = make_float4(cv[4], cv[5], cv[6], cv[7]);
            qd[2] = make_float4(sv[0], sv[1], sv[2], sv[3]);
            qd[3] = make_float4(sv[4], sv[5], sv[6], sv[7]);
        } else {
            float4* kd = (float4*)(sKp + tok * KPAD);
            kd[0] = make_float4(cv[0], cv[1], cv[2], cv[3]);
            kd[1] = make_float4(cv[4], cv[5], cv[6], cv[7]);
            kd[2] = make_float4(sv[0], sv[1], sv[2], sv[3]);
            kd[3] = make_float4(sv[4], sv[5], sv[6], sv[7]);
        }
    }
    __syncthreads();

    // kpsum partial (deterministic), transposed layout
    if (tid < 16) {
        float s = 0.0f;
        for (int t = 0; t < CH; t++) s += sKp[t * KPAD + tid];
        g_kps[tid * NBLK + blk] = s;
    }

    // ---- pass 2: Gpart = Kp^T @ x_chunk, thread owns 4 e-columns ----
    uint64_t ga[8][4];
#pragma unroll
    for (int p2 = 0; p2 < 8; p2++)
#pragma unroll
        for (int c = 0; c < 4; c++) ga[p2][c] = 0ull;

    const float4* xp = (const float4*)(x + (size_t)row0 * E) + tid;

    for (int t0 = 0; t0 < CH; t0 += 4) {
        float4 v[4];
#pragma unroll
        for (int u = 0; u < 4; u++) v[u] = xp[(size_t)(t0 + u) * (E / 4)];
#pragma unroll
        for (int u = 0; u < 4; u++) {
            const ulonglong2* kr = (const ulonglong2*)(sKp + (t0 + u) * KPAD);
            ulonglong2 k0 = kr[0], k1 = kr[1], k2 = kr[2], k3 = kr[3];
            uint64_t kp[8] = {k0.x, k0.y, k1.x, k1.y, k2.x, k2.y, k3.x, k3.y};
            float xa[4] = {v[u].x, v[u].y, v[u].z, v[u].w};
#pragma unroll
            for (int c = 0; c < 4; c++) {
                uint64_t xc = pack2(xa[c], xa[c]);
#pragma unroll
                for (int p2 = 0; p2 < 8; p2++) fma2(ga[p2][c], kp[p2], xc);
            }
        }
    }

    float* dst = g_Gpart + (size_t)blk * F * E + tid * 4;
#pragma unroll
    for (int p2 = 0; p2 < 8; p2++) {
        float2 u0 = unpack2(ga[p2][0]);
        float2 u1 = unpack2(ga[p2][1]);
        float2 u2 = unpack2(ga[p2][2]);
        float2 u3 = unpack2(ga[p2][3]);
        ((float4*)(dst + (size_t)(2 * p2) * E))[0]     = make_float4(u0.x, u1.x, u2.x, u3.x);
        ((float4*)(dst + (size_t)(2 * p2 + 1) * E))[0] = make_float4(u0.y, u1.y, u2.y, u3.y);
    }
}

// ============================================================
// k_sp: per (es,b,spg): reduce Gpart over 32 sp chunks for e-slice
//       [es*64,+64), then Spart = Gslice @ Wv_slice.  grid (16,4,2).
// ============================================================
__global__ void __launch_bounds__(128) k_sp(const float* __restrict__ Wv) {
    int es  = blockIdx.x;
    int b   = blockIdx.y;
    int spg = blockIdx.z;
    int e0 = es * 64;
    int tid = threadIdx.x;
    __shared__ __align__(16) float sG[16][68];
    __shared__ __align__(16) float sWv[64][64];

    int f  = tid >> 3;
    int eo = (tid & 7) * 8;

    float4 a0 = make_float4(0.f, 0.f, 0.f, 0.f);
    float4 a1 = make_float4(0.f, 0.f, 0.f, 0.f);
    const float* base = g_Gpart + (size_t)(b * SPB + spg * 32) * (F * E) + (size_t)f * E + e0 + eo;
#pragma unroll 8
    for (int sp = 0; sp < 32; sp++) {
        const float4* p = (const float4*)(base + (size_t)sp * (F * E));
        float4 v0 = p[0], v1 = p[1];
        a0.x += v0.x; a0.y += v0.y; a0.z += v0.z; a0.w += v0.w;
        a1.x += v1.x; a1.y += v1.y; a1.z += v1.z; a1.w += v1.w;
    }
    *(float4*)&sG[f][eo]     = a0;
    *(float4*)&sG[f][eo + 4] = a1;

    const float4* wsrc = (const float4*)(Wv + (size_t)e0 * D);
    for (int i = tid; i < 64 * 16; i += 128)
        ((float4*)sWv)[i] = wsrc[i];
    __syncthreads();

    int dg = (tid & 7) * 8;
    float ac[8] = {0.f, 0.f, 0.f, 0.f, 0.f, 0.f, 0.f, 0.f};
#pragma unroll 4
    for (int e = 0; e < 64; e++) {
        float g = sG[f][e];
        float4 w0 = *(const float4*)&sWv[e][dg];
        float4 w1 = *(const float4*)&sWv[e][dg + 4];
        ac[0] += g * w0.x; ac[1] += g * w0.y; ac[2] += g * w0.z; ac[3] += g * w0.w;
        ac[4] += g * w1.x; ac[5] += g * w1.y; ac[6] += g * w1.z; ac[7] += g * w1.w;
    }
    float* dst = g_Spart + ((size_t)(spg * 16 + es) * B + b) * (F * D) + f * D + dg;
    *(float4*)dst       = make_float4(ac[0], ac[1], ac[2], ac[3]);
    *(float4*)(dst + 4) = make_float4(ac[4], ac[5], ac[6], ac[7]);
}

// ============================================================
// k_y: prologue builds S[b] in smem (Spart 32-slice sum + kpsum*bv),
//      then y = qP @ S.  256 blocks x 256 thr, 128 tokens/block.
// ============================================================
__global__ void __launch_bounds__(256) k_y(float* __restrict__ y,
                                           const float* __restrict__ bv) {
    __shared__ __align__(16) float sS[F * D];
    __shared__ float skp[16];
    __shared__ float sred[64];
    int tid = threadIdx.x;
    int bid = blockIdx.x;
    int b = bid >> 6;  // 64 blocks per batch

    // kpsum partials: 64 threads, f = t>>2, quarter = t&3
    if (tid < 64) {
        int f = tid >> 2, part = tid & 3;
        const float4* kp4 = (const float4*)(g_kps + f * NBLK + b * 64 + part * 16);
        float4 v0 = kp4[0], v1 = kp4[1], v2 = kp4[2], v3 = kp4[3];
        sred[tid] = ((v0.x + v0.y) + (v0.z + v0.w)) + ((v1.x + v1.y) + (v1.z + v1.w))
                  + ((v2.x + v2.y) + (v2.z + v2.w)) + ((v3.x + v3.y) + (v3.z + v3.w));
    }

    // Spart 32-slice sum: thread owns 4 fd (one float4)
    float4 a = make_float4(0.f, 0.f, 0.f, 0.f);
#pragma unroll 8
    for (int sl = 0; sl < NSL; sl++) {
        float4 v = ((const float4*)(g_Spart + ((size_t)sl * B + b) * (F * D)))[tid];
        a.x += v.x; a.y += v.y; a.z += v.z; a.w += v.w;
    }
    __syncthreads();
    if (tid < 16)
        skp[tid] = (sred[4 * tid] + sred[4 * tid + 1]) + (sred[4 * tid + 2] + sred[4 * tid + 3]);
    __syncthreads();

    {
        int f = tid >> 4;
        int d = (tid * 4) & 63;
        float kv = skp[f];
        float4 bvv = *(const float4*)(bv + d);
        ((float4*)sS)[tid] = make_float4(a.x + kv * bvv.x, a.y + kv * bvv.y,
                                         a.z + kv * bvv.z, a.w + kv * bvv.w);
    }
    __syncthreads();

    int tl = tid & 127, g = tid >> 7;
    int t0 = bid * 128 + tl;

    const float4* qa = (const float4*)(g_qP + (size_t)t0 * F);
    float4 a0 = qa[0], a1 = qa[1], a2 = qa[2], a3 = qa[3];
    float qv[16] = {a0.x, a0.y, a0.z, a0.w, a1.x, a1.y, a1.z, a1.w,
                    a2.x, a2.y, a2.z, a2.w, a3.x, a3.y, a3.z, a3.w};

    uint64_t acc[16];
#pragma unroll
    for (int p = 0; p < 16; p++) acc[p] = 0ull;

#pragma unroll
    for (int f = 0; f < F; f++) {
        const ulonglong2* sr = (const ulonglong2*)(sS + f * D + g * 32);
        uint64_t qf = pack2(qv[f], qv[f]);
#pragma unroll
        for (int p = 0; p < 8; p++) {
            ulonglong2 w = sr[p];
            fma2(acc[2 * p],     qf, w.x);
            fma2(acc[2 * p + 1], qf, w.y);
        }
    }

    float4* dA = (float4*)(y + (size_t)t0 * D + g * 32);
#pragma unroll
    for (int p = 0; p < 8; p++) {
        float2 lo = unpack2(acc[2 * p]);
        float2 hi = unpack2(acc[2 * p + 1]);
        dA[p] = make_float4(lo.x, lo.y, hi.x, hi.y);
    }
}

// ============================================================
extern "C" void kernel_launch(void* const* d_in, const int* in_sizes, int n_in,
                              void* d_out, int out_size) {
    const float* x  = (const float*)d_in[0];
    const float* w  = (const float*)d_in[1];
    const float* Wq = (const float*)d_in[2];
    const float* bq = (const float*)d_in[3];
    const float* Wk = (const float*)d_in[4];
    const float* bk = (const float*)d_in[5];
    const float* Wv = (const float*)d_in[6];
    const float* bv = (const float*)d_in[7];
    float* y = (float*)d_out;

    cudaFuncSetAttribute(k_fused, cudaFuncAttributeMaxDynamicSharedMemorySize,
                         SMEM_FLOATS * 4);

    k_fold<<<64, 256>>>(Wq, bq, Wk, bk, w);
    k_fused<<<NBLK, 256, SMEM_FLOATS * 4>>>(x);
    dim3 gsp(16, 4, 2);
    k_sp<<<gsp, 128>>>(Wv);
    k_y<<<256, 256>>>(y, bv);
}

// round 12
// speedup vs baseline: 2.8862x; 1.0557x over previous
#include <cuda_runtime.h>
#include <cstdint>

// Problem constants
#define B   4
#define T   8192
#define BT  32768     // B*T
#define E   1024      // n_embd
#define D   64        // d_head
#define M   8         // M_FEAT
#define F   16        // 2*M feature dim
#define CH  128       // tokens per fused block
#define NBLK (BT/CH)  // 256 blocks
#define SPB (T/CH)    // 64 chunks per batch
#define KPAD 20       // sKp row stride
#define XS  33        // sX row stride (odd -> conflict-free scalar access)
#define PPAD 20       // sPart row stride
#define NSL 32        // S partial slices (16 es x 2 spg)

// smem layout (floats) for k_fused
#define OFF_WF 0          // 16384 floats (all Wf)
#define OFF_X0 16384      // 4224 floats
#define OFF_X1 20608      // 4224 floats
#define OFF_KP 24832      // 2560 floats
#define OFF_BF 27392      // 16
#define SMEM_FLOATS 27408
// sPart [8][128][PPAD] = 20480 floats aliases [0..20480) after pass1

// -------- scratch (device globals; no allocation) --------
__device__ __align__(16) float g_Wf[E * F];
__device__ __align__(16) float g_bf[F];
__device__ __align__(16) float g_qP[(size_t)BT * F];
__device__ __align__(16) float g_Gpart[(size_t)NBLK * F * E]; // 16 MB
__device__ __align__(16) float g_Spart[NSL * B * F * D];      // 512 KB
__device__ __align__(16) float g_kps[F * NBLK];               // transposed [f][blk]
__device__ __align__(16) float g_S[B * F * D];                // final S

// -------- packed f32x2 helpers --------
__device__ __forceinline__ uint64_t pack2(float lo, float hi) {
    uint64_t r;
    asm("mov.b64 %0, {%1, %2};" : "=l"(r) : "f"(lo), "f"(hi));
    return r;
}
__device__ __forceinline__ float2 unpack2(uint64_t v) {
    float2 r;
    asm("mov.b64 {%0, %1}, %2;" : "=f"(r.x), "=f"(r.y) : "l"(v));
    return r;
}
__device__ __forceinline__ void fma2(uint64_t& d, uint64_t a, uint64_t b) {
    asm("fma.rn.f32x2 %0, %1, %2, %0;" : "+l"(d) : "l"(a), "l"(b));
}

// ============================================================
// Kernel 0: fold weights  Wf = [Wq@w | Wk@w], bf = [bq@w | bk@w]
// ============================================================
__global__ void k_fold(const float* __restrict__ Wq, const float* __restrict__ bq,
                       const float* __restrict__ Wk, const float* __restrict__ bk,
                       const float* __restrict__ w) {
    __shared__ float sw[D * M];
    int t = threadIdx.x;
    sw[t] = w[t];
    sw[t + 256] = w[t + 256];
    __syncthreads();

    int idx = blockIdx.x * blockDim.x + t;
    if (idx < E * F) {
        int j = idx & 15;
        int k = idx >> 4;
        const float* W = (j < 8) ? Wq : Wk;
        int jm = j & 7;
        const float4* Wr = (const float4*)(W + (size_t)k * D);
        float s = 0.0f;
#pragma unroll
        for (int d4 = 0; d4 < 16; d4++) {
            float4 wv = Wr[d4];
            s += wv.x * sw[(d4 * 4 + 0) * M + jm];
            s += wv.y * sw[(d4 * 4 + 1) * M + jm];
            s += wv.z * sw[(d4 * 4 + 2) * M + jm];
            s += wv.w * sw[(d4 * 4 + 3) * M + jm];
        }
        g_Wf[k * F + j] = s;
    }
    if (blockIdx.x == 0 && idx < F) {
        int jm = idx & 7;
        const float* bb = (idx < 8) ? bq : bk;
        float s = 0.0f;
#pragma unroll 8
        for (int d = 0; d < D; d++) s += bb[d] * sw[d * M + jm];
        g_bf[idx] = s;
    }
}

// ============================================================
// Fused kernel: pass1 projection+features, pass2 Gpart.
// ============================================================
__global__ void __launch_bounds__(256, 2) k_fused(const float* __restrict__ x) {
    extern __shared__ __align__(16) float smem[];
    float* sWf   = smem + OFF_WF;
    float* sKp   = smem + OFF_KP;
    float* sbf   = smem + OFF_BF;
    float* sPart = smem;  // alias, used after pass1

    int tid = threadIdx.x;
    int blk = blockIdx.x;
    int row0 = blk * CH;
    int tg = tid & 31;
    int h  = tid >> 5;

    // preload all Wf (64 KB) + bf
    for (int i = tid; i < E * F / 4; i += 256)
        ((float4*)sWf)[i] = ((const float4*)g_Wf)[i];
    if (tid < 16) sbf[tid] = g_bf[tid];

    uint64_t acc[4][8];
#pragma unroll
    for (int u = 0; u < 4; u++)
#pragma unroll
        for (int q = 0; q < 8; q++) acc[u][q] = 0ull;

    const float4* xg = (const float4*)x;

    int t_[4], c4_[4];
#pragma unroll
    for (int q = 0; q < 4; q++) { int idx = q * 256 + tid; t_[q] = idx >> 3; c4_[q] = idx & 7; }

    float4 pre[4];

    // prefetch + store chunk 0 into buf0
#pragma unroll
    for (int q = 0; q < 4; q++)
        pre[q] = xg[(size_t)(row0 + t_[q]) * (E / 4) + c4_[q]];
    {
        float* sX = smem + OFF_X0;
#pragma unroll
        for (int q = 0; q < 4; q++) {
            int base = t_[q] * XS + c4_[q] * 4;
            sX[base + 0] = pre[q].x;
            sX[base + 1] = pre[q].y;
            sX[base + 2] = pre[q].z;
            sX[base + 3] = pre[q].w;
        }
    }
    __syncthreads();

    for (int ch = 0; ch < 32; ch++) {
        int cur = ch & 1;
        float* sX = smem + (cur ? OFF_X1 : OFF_X0);
        const float* sW = sWf + ch * 512;
        if (ch < 31) {
#pragma unroll
            for (int q = 0; q < 4; q++)
                pre[q] = xg[(size_t)(row0 + t_[q]) * (E / 4) + (ch + 1) * 8 + c4_[q]];
        }
#pragma unroll
        for (int c = 0; c < 4; c++) {
            int kl = 4 * h + c;
            const ulonglong2* wr = (const ulonglong2*)(sW + kl * 16);
            ulonglong2 w0 = wr[0], w1 = wr[1], w2 = wr[2], w3 = wr[3];
            uint64_t wv[8] = {w0.x, w0.y, w1.x, w1.y, w2.x, w2.y, w3.x, w3.y};
#pragma unroll
            for (int u = 0; u < 4; u++) {
                float xv = sX[(tg + 32 * u) * XS + kl];
                uint64_t xx = pack2(xv, xv);
#pragma unroll
                for (int q = 0; q < 8; q++) fma2(acc[u][q], wv[q], xx);
            }
        }
        if (ch < 31) {
            float* dX = smem + (cur ? OFF_X0 : OFF_X1);
#pragma unroll
            for (int q = 0; q < 4; q++) {
                int base = t_[q] * XS + c4_[q] * 4;
                dX[base + 0] = pre[q].x;
                dX[base + 1] = pre[q].y;
                dX[base + 2] = pre[q].z;
                dX[base + 3] = pre[q].w;
            }
        }
        __syncthreads();
    }

    // ---- write h-split partials: sPart[h][tok][f] (aliases Wf+buf0; safe) ----
#pragma unroll
    for (int u = 0; u < 4; u++) {
        int tok = tg + 32 * u;
        float* dp = sPart + h * 2560 + tok * PPAD;
        float2 a0 = unpack2(acc[u][0]);
        float2 a1 = unpack2(acc[u][1]);
        float2 a2 = unpack2(acc[u][2]);
        float2 a3 = unpack2(acc[u][3]);
        float2 a4 = unpack2(acc[u][4]);
        float2 a5 = unpack2(acc[u][5]);
        float2 a6 = unpack2(acc[u][6]);
        float2 a7 = unpack2(acc[u][7]);
        *(float4*)(dp + 0)  = make_float4(a0.x, a0.y, a1.x, a1.y);
        *(float4*)(dp + 4)  = make_float4(a2.x, a2.y, a3.x, a3.y);
        *(float4*)(dp + 8)  = make_float4(a4.x, a4.y, a5.x, a5.y);
        *(float4*)(dp + 12) = make_float4(a6.x, a6.y, a7.x, a7.y);
    }
    __syncthreads();

    // ---- combine + sincos: thread (tok, g) handles 8 features ----
    {
        int tok = tid & 127;
        int g = tid >> 7;
        float4 P0 = make_float4(0.f, 0.f, 0.f, 0.f);
        float4 P1 = make_float4(0.f, 0.f, 0.f, 0.f);
#pragma unroll
        for (int h2 = 0; h2 < 8; h2++) {
            float4 v0 = *(const float4*)(sPart + h2 * 2560 + tok * PPAD + g * 8);
            float4 v1 = *(const float4*)(sPart + h2 * 2560 + tok * PPAD + g * 8 + 4);
            P0.x += v0.x; P0.y += v0.y; P0.z += v0.z; P0.w += v0.w;
            P1.x += v1.x; P1.y += v1.y; P1.z += v1.z; P1.w += v1.w;
        }
        float p[8] = {P0.x + sbf[8 * g + 0], P0.y + sbf[8 * g + 1],
                      P0.z + sbf[8 * g + 2], P0.w + sbf[8 * g + 3],
                      P1.x + sbf[8 * g + 4], P1.y + sbf[8 * g + 5],
                      P1.z + sbf[8 * g + 6], P1.w + sbf[8 * g + 7]};
        const float inv = 0.35355339059327376f;
        float cv[8], sv[8];
#pragma unroll
        for (int j = 0; j < 8; j++) {
            float s, c;
            __sincosf(p[j], &s, &c);
            cv[j] = c * inv; sv[j] = s * inv;
        }
        if (g == 0) {
            float4* qd = (float4*)(g_qP + (size_t)(row0 + tok) * F);
            qd[0] = make_float4(cv[0], cv[1], cv[2], cv[3]);
            qd[1] = make_float4(cv[4], cv[5], cv[6], cv[7]);
            qd[2] = make_float4(sv[0], sv[1], sv[2], sv[3]);
            qd[3] = make_float4(sv[4], sv[5], sv[6], sv[7]);
        } else {
            float4* kd = (float4*)(sKp + tok * KPAD);
            kd[0] = make_float4(cv[0], cv[1], cv[2], cv[3]);
            kd[1] = make_float4(cv[4], cv[5], cv[6], cv[7]);
            kd[2] = make_float4(sv[0], sv[1], sv[2], sv[3]);
            kd[3] = make_float4(sv[4], sv[5], sv[6], sv[7]);
        }
    }
    __syncthreads();

    // kpsum partial (deterministic), transposed layout
    if (tid < 16) {
        float s = 0.0f;
        for (int t = 0; t < CH; t++) s += sKp[t * KPAD + tid];
        g_kps[tid * NBLK + blk] = s;
    }

    // ---- pass 2: Gpart = Kp^T @ x_chunk, software-pipelined LDG ----
    uint64_t ga[8][4];
#pragma unroll
    for (int p2 = 0; p2 < 8; p2++)
#pragma unroll
        for (int c = 0; c < 4; c++) ga[p2][c] = 0ull;

    const float4* xp = (const float4*)(x + (size_t)row0 * E) + tid;

    float4 v0 = xp[0];
    float4 v1 = xp[E / 4];
#pragma unroll 4
    for (int t0 = 0; t0 < CH; t0 += 2) {
        float4 n0, n1;
        if (t0 < CH - 2) {
            n0 = xp[(size_t)(t0 + 2) * (E / 4)];
            n1 = xp[(size_t)(t0 + 3) * (E / 4)];
        }
#pragma unroll
        for (int u = 0; u < 2; u++) {
            const ulonglong2* kr = (const ulonglong2*)(sKp + (t0 + u) * KPAD);
            ulonglong2 k0 = kr[0], k1 = kr[1], k2 = kr[2], k3 = kr[3];
            uint64_t kp[8] = {k0.x, k0.y, k1.x, k1.y, k2.x, k2.y, k3.x, k3.y};
            float4 vv = u ? v1 : v0;
            float xa[4] = {vv.x, vv.y, vv.z, vv.w};
#pragma unroll
            for (int c = 0; c < 4; c++) {
                uint64_t xc = pack2(xa[c], xa[c]);
#pragma unroll
                for (int p2 = 0; p2 < 8; p2++) fma2(ga[p2][c], kp[p2], xc);
            }
        }
        v0 = n0; v1 = n1;
    }

    float* dst = g_Gpart + (size_t)blk * F * E + tid * 4;
#pragma unroll
    for (int p2 = 0; p2 < 8; p2++) {
        float2 u0 = unpack2(ga[p2][0]);
        float2 u1 = unpack2(ga[p2][1]);
        float2 u2 = unpack2(ga[p2][2]);
        float2 u3 = unpack2(ga[p2][3]);
        ((float4*)(dst + (size_t)(2 * p2) * E))[0]     = make_float4(u0.x, u1.x, u2.x, u3.x);
        ((float4*)(dst + (size_t)(2 * p2 + 1) * E))[0] = make_float4(u0.y, u1.y, u2.y, u3.y);
    }
}

// ============================================================
// k_sp: per (es,b,spg): reduce Gpart over 32 sp chunks for e-slice,
//       then Spart = Gslice @ Wv_slice.  grid (16,4,2), 128 thr.
// ============================================================
__global__ void __launch_bounds__(128) k_sp(const float* __restrict__ Wv) {
    int es  = blockIdx.x;
    int b   = blockIdx.y;
    int spg = blockIdx.z;
    int e0 = es * 64;
    int tid = threadIdx.x;
    __shared__ __align__(16) float sG[16][68];
    __shared__ __align__(16) float sWv[64][64];

    int f  = tid >> 3;
    int eo = (tid & 7) * 8;

    float4 a0 = make_float4(0.f, 0.f, 0.f, 0.f);
    float4 a1 = make_float4(0.f, 0.f, 0.f, 0.f);
    const float* base = g_Gpart + (size_t)(b * SPB + spg * 32) * (F * E) + (size_t)f * E + e0 + eo;
#pragma unroll 8
    for (int sp = 0; sp < 32; sp++) {
        const float4* p = (const float4*)(base + (size_t)sp * (F * E));
        float4 w0 = p[0], w1 = p[1];
        a0.x += w0.x; a0.y += w0.y; a0.z += w0.z; a0.w += w0.w;
        a1.x += w1.x; a1.y += w1.y; a1.z += w1.z; a1.w += w1.w;
    }
    *(float4*)&sG[f][eo]     = a0;
    *(float4*)&sG[f][eo + 4] = a1;

    const float4* wsrc = (const float4*)(Wv + (size_t)e0 * D);
    for (int i = tid; i < 64 * 16; i += 128)
        ((float4*)sWv)[i] = wsrc[i];
    __syncthreads();

    int dg = (tid & 7) * 8;
    float ac[8] = {0.f, 0.f, 0.f, 0.f, 0.f, 0.f, 0.f, 0.f};
#pragma unroll 4
    for (int e = 0; e < 64; e++) {
        float g = sG[f][e];
        float4 w0 = *(const float4*)&sWv[e][dg];
        float4 w1 = *(const float4*)&sWv[e][dg + 4];
        ac[0] += g * w0.x; ac[1] += g * w0.y; ac[2] += g * w0.z; ac[3] += g * w0.w;
        ac[4] += g * w1.x; ac[5] += g * w1.y; ac[6] += g * w1.z; ac[7] += g * w1.w;
    }
    float* dst = g_Spart + ((size_t)(spg * 16 + es) * B + b) * (F * D) + f * D + dg;
    *(float4*)dst       = make_float4(ac[0], ac[1], ac[2], ac[3]);
    *(float4*)(dst + 4) = make_float4(ac[4], ac[5], ac[6], ac[7]);
}

// ============================================================
// k_sfin: S[b] = sum_sl Spart + kpsum*bv. grid 4 (one per batch), 256 thr.
// ============================================================
__global__ void __launch_bounds__(256) k_sfin(const float* __restrict__ bv) {
    __shared__ float skp[16];
    int b = blockIdx.x;
    int tid = threadIdx.x;

    if (tid < 16) {
        const float4* kp4 = (const float4*)(g_kps + tid * NBLK + b * 64);
        float s = 0.0f;
#pragma unroll
        for (int i = 0; i < 16; i++) {
            float4 v = kp4[i];
            s += ((v.x + v.y) + (v.z + v.w));
        }
        skp[tid] = s;
    }
    __syncthreads();

    // output float4 index fd4 = tid (256 = F*D/4)
    float4 a = make_float4(0.f, 0.f, 0.f, 0.f);
#pragma unroll 8
    for (int sl = 0; sl < NSL; sl++) {
        float4 v = ((const float4*)g_Spart)[(sl * 4 + b) * 256 + tid];
        a.x += v.x; a.y += v.y; a.z += v.z; a.w += v.w;
    }
    int f = tid >> 4;
    int d4 = tid & 15;
    float kv = skp[f];
    float4 bvv = ((const float4*)bv)[d4];
    ((float4*)g_S)[b * 256 + tid] = make_float4(a.x + kv * bvv.x, a.y + kv * bvv.y,
                                                a.z + kv * bvv.z, a.w + kv * bvv.w);
}

// ============================================================
// k_y: y = qP @ S.  256 blocks x 256 thr, 128 tokens/block.
// ============================================================
__global__ void __launch_bounds__(256) k_y(float* __restrict__ y) {
    __shared__ __align__(16) float sS[F * D];
    int tid = threadIdx.x;
    int bid = blockIdx.x;
    int b = bid >> 6;
    ((float4*)sS)[tid] = ((const float4*)g_S)[b * 256 + tid];
    __syncthreads();

    int tl = tid & 127, g = tid >> 7;
    int t0 = bid * 128 + tl;

    const float4* qa = (const float4*)(g_qP + (size_t)t0 * F);
    float4 a0 = qa[0], a1 = qa[1], a2 = qa[2], a3 = qa[3];
    float qv[16] = {a0.x, a0.y, a0.z, a0.w, a1.x, a1.y, a1.z, a1.w,
                    a2.x, a2.y, a2.z, a2.w, a3.x, a3.y, a3.z, a3.w};

    uint64_t acc[16];
#pragma unroll
    for (int p = 0; p < 16; p++) acc[p] = 0ull;

#pragma unroll
    for (int f = 0; f < F; f++) {
        const ulonglong2* sr = (const ulonglong2*)(sS + f * D + g * 32);
        uint64_t qf = pack2(qv[f], qv[f]);
#pragma unroll
        for (int p = 0; p < 8; p++) {
            ulonglong2 w = sr[p];
            fma2(acc[2 * p],     qf, w.x);
            fma2(acc[2 * p + 1], qf, w.y);
        }
    }

    float4* dA = (float4*)(y + (size_t)t0 * D + g * 32);
#pragma unroll
    for (int p = 0; p < 8; p++) {
        float2 lo = unpack2(acc[2 * p]);
        float2 hi = unpack2(acc[2 * p + 1]);
        dA[p] = make_float4(lo.x, lo.y, hi.x, hi.y);
    }
}

// ============================================================
extern "C" void kernel_launch(void* const* d_in, const int* in_sizes, int n_in,
                              void* d_out, int out_size) {
    const float* x  = (const float*)d_in[0];
    const float* w  = (const float*)d_in[1];
    const float* Wq = (const float*)d_in[2];
    const float* bq = (const float*)d_in[3];
    const float* Wk = (const float*)d_in[4];
    const float* bk = (const float*)d_in[5];
    const float* Wv = (const float*)d_in[6];
    const float* bv = (const float*)d_in[7];
    float* y = (float*)d_out;

    cudaFuncSetAttribute(k_fused, cudaFuncAttributeMaxDynamicSharedMemorySize,
                         SMEM_FLOATS * 4);

    k_fold<<<64, 256>>>(Wq, bq, Wk, bk, w);
    k_fused<<<NBLK, 256, SMEM_FLOATS * 4>>>(x);
    dim3 gsp(16, 4, 2);
    k_sp<<<gsp, 128>>>(Wv);
    k_sfin<<<4, 256>>>(bv);
    k_y<<<256, 256>>>(y);
}

// round 17
// speedup vs baseline: 2.9545x; 1.0237x over previous
#include <cuda_runtime.h>
#include <cstdint>

// Problem constants
#define B   4
#define T   8192
#define BT  32768     // B*T
#define E   1024      // n_embd
#define D   64        // d_head
#define M   8         // M_FEAT
#define F   16        // 2*M feature dim
#define CH  128       // tokens per fused block
#define NBLK (BT/CH)  // 256 blocks
#define SPB (T/CH)    // 64 chunks per batch
#define KPAD 20       // sKp row stride
#define XS  33        // sX row stride (odd -> conflict-free scalar access)
#define PPAD 20       // sPart row stride
#define NSL 64        // S partial slices (16 es x 4 spg)

// smem layout (floats) for k_fused
#define OFF_WF 0          // 16384 floats (all Wf)
#define OFF_X0 16384      // 4224 floats
#define OFF_X1 20608      // 4224 floats
#define OFF_KP 24832      // 2560 floats
#define OFF_BF 27392      // 16
#define SMEM_FLOATS 27408
// sPart [8][128][PPAD] = 20480 floats aliases [0..20480) after pass1

// -------- scratch (device globals; no allocation) --------
__device__ __align__(16) float g_Wf[E * F];
__device__ __align__(16) float g_bf[F];
__device__ __align__(16) float g_qP[(size_t)BT * F];
__device__ __align__(16) float g_Gpart[(size_t)NBLK * F * E]; // 16 MB
__device__ __align__(16) float g_Spart[NSL * B * F * D];      // 1 MB
__device__ __align__(16) float g_kps[F * NBLK];               // transposed [f][blk]
__device__ __align__(16) float g_S[B * F * D];                // final S

// -------- packed f32x2 helpers --------
__device__ __forceinline__ uint64_t pack2(float lo, float hi) {
    uint64_t r;
    asm("mov.b64 %0, {%1, %2};" : "=l"(r) : "f"(lo), "f"(hi));
    return r;
}
__device__ __forceinline__ float2 unpack2(uint64_t v) {
    float2 r;
    asm("mov.b64 {%0, %1}, %2;" : "=f"(r.x), "=f"(r.y) : "l"(v));
    return r;
}
__device__ __forceinline__ void fma2(uint64_t& d, uint64_t a, uint64_t b) {
    asm("fma.rn.f32x2 %0, %1, %2, %0;" : "+l"(d) : "l"(a), "l"(b));
}

// ============================================================
// Kernel 0: fold weights  Wf = [Wq@w | Wk@w], bf = [bq@w | bk@w]
// ============================================================
__global__ void k_fold(const float* __restrict__ Wq, const float* __restrict__ bq,
                       const float* __restrict__ Wk, const float* __restrict__ bk,
                       const float* __restrict__ w) {
    __shared__ float sw[D * M];
    int t = threadIdx.x;
    sw[t] = w[t];
    sw[t + 256] = w[t + 256];
    __syncthreads();

    int idx = blockIdx.x * blockDim.x + t;
    if (idx < E * F) {
        int j = idx & 15;
        int k = idx >> 4;
        const float* W = (j < 8) ? Wq : Wk;
        int jm = j & 7;
        const float4* Wr = (const float4*)(W + (size_t)k * D);
        float s = 0.0f;
#pragma unroll
        for (int d4 = 0; d4 < 16; d4++) {
            float4 wv = Wr[d4];
            s += wv.x * sw[(d4 * 4 + 0) * M + jm];
            s += wv.y * sw[(d4 * 4 + 1) * M + jm];
            s += wv.z * sw[(d4 * 4 + 2) * M + jm];
            s += wv.w * sw[(d4 * 4 + 3) * M + jm];
        }
        g_Wf[k * F + j] = s;
    }
    if (blockIdx.x == 0 && idx < F) {
        int jm = idx & 7;
        const float* bb = (idx < 8) ? bq : bk;
        float s = 0.0f;
#pragma unroll 8
        for (int d = 0; d < D; d++) s += bb[d] * sw[d * M + jm];
        g_bf[idx] = s;
    }
}

// ============================================================
// Fused kernel: pass1 projection+features, pass2 Gpart.
// ============================================================
__global__ void __launch_bounds__(256, 2) k_fused(const float* __restrict__ x) {
    extern __shared__ __align__(16) float smem[];
    float* sWf   = smem + OFF_WF;
    float* sKp   = smem + OFF_KP;
    float* sbf   = smem + OFF_BF;
    float* sPart = smem;  // alias, used after pass1

    int tid = threadIdx.x;
    int blk = blockIdx.x;
    int row0 = blk * CH;
    int tg = tid & 31;
    int h  = tid >> 5;

    // preload all Wf (64 KB) + bf
    for (int i = tid; i < E * F / 4; i += 256)
        ((float4*)sWf)[i] = ((const float4*)g_Wf)[i];
    if (tid < 16) sbf[tid] = g_bf[tid];

    uint64_t acc[4][8];
#pragma unroll
    for (int u = 0; u < 4; u++)
#pragma unroll
        for (int q = 0; q < 8; q++) acc[u][q] = 0ull;

    const float4* xg = (const float4*)x;

    int t_[4], c4_[4];
#pragma unroll
    for (int q = 0; q < 4; q++) { int idx = q * 256 + tid; t_[q] = idx >> 3; c4_[q] = idx & 7; }

    float4 pre[4];

    // prefetch + store chunk 0 into buf0
#pragma unroll
    for (int q = 0; q < 4; q++)
        pre[q] = xg[(size_t)(row0 + t_[q]) * (E / 4) + c4_[q]];
    {
        float* sX = smem + OFF_X0;
#pragma unroll
        for (int q = 0; q < 4; q++) {
            int base = t_[q] * XS + c4_[q] * 4;
            sX[base + 0] = pre[q].x;
            sX[base + 1] = pre[q].y;
            sX[base + 2] = pre[q].z;
            sX[base + 3] = pre[q].w;
        }
    }
    __syncthreads();

    for (int ch = 0; ch < 32; ch++) {
        int cur = ch & 1;
        float* sX = smem + (cur ? OFF_X1 : OFF_X0);
        const float* sW = sWf + ch * 512;
        if (ch < 31) {
#pragma unroll
            for (int q = 0; q < 4; q++)
                pre[q] = xg[(size_t)(row0 + t_[q]) * (E / 4) + (ch + 1) * 8 + c4_[q]];
        }
#pragma unroll
        for (int c = 0; c < 4; c++) {
            int kl = 4 * h + c;
            const ulonglong2* wr = (const ulonglong2*)(sW + kl * 16);
            ulonglong2 w0 = wr[0], w1 = wr[1], w2 = wr[2], w3 = wr[3];
            uint64_t wv[8] = {w0.x, w0.y, w1.x, w1.y, w2.x, w2.y, w3.x, w3.y};
#pragma unroll
            for (int u = 0; u < 4; u++) {
                float xv = sX[(tg + 32 * u) * XS + kl];
                uint64_t xx = pack2(xv, xv);
#pragma unroll
                for (int q = 0; q < 8; q++) fma2(acc[u][q], wv[q], xx);
            }
        }
        if (ch < 31) {
            float* dX = smem + (cur ? OFF_X0 : OFF_X1);
#pragma unroll
            for (int q = 0; q < 4; q++) {
                int base = t_[q] * XS + c4_[q] * 4;
                dX[base + 0] = pre[q].x;
                dX[base + 1] = pre[q].y;
                dX[base + 2] = pre[q].z;
                dX[base + 3] = pre[q].w;
            }
        }
        __syncthreads();
    }

    // ---- write h-split partials: sPart[h][tok][f] (aliases Wf+buf0; safe) ----
#pragma unroll
    for (int u = 0; u < 4; u++) {
        int tok = tg + 32 * u;
        float* dp = sPart + h * 2560 + tok * PPAD;
        float2 a0 = unpack2(acc[u][0]);
        float2 a1 = unpack2(acc[u][1]);
        float2 a2 = unpack2(acc[u][2]);
        float2 a3 = unpack2(acc[u][3]);
        float2 a4 = unpack2(acc[u][4]);
        float2 a5 = unpack2(acc[u][5]);
        float2 a6 = unpack2(acc[u][6]);
        float2 a7 = unpack2(acc[u][7]);
        *(float4*)(dp + 0)  = make_float4(a0.x, a0.y, a1.x, a1.y);
        *(float4*)(dp + 4)  = make_float4(a2.x, a2.y, a3.x, a3.y);
        *(float4*)(dp + 8)  = make_float4(a4.x, a4.y, a5.x, a5.y);
        *(float4*)(dp + 12) = make_float4(a6.x, a6.y, a7.x, a7.y);
    }
    __syncthreads();

    // ---- combine + sincos: thread (tok, g) handles 8 features ----
    {
        int tok = tid & 127;
        int g = tid >> 7;
        float4 P0 = make_float4(0.f, 0.f, 0.f, 0.f);
        float4 P1 = make_float4(0.f, 0.f, 0.f, 0.f);
#pragma unroll
        for (int h2 = 0; h2 < 8; h2++) {
            float4 v0 = *(const float4*)(sPart + h2 * 2560 + tok * PPAD + g * 8);
            float4 v1 = *(const float4*)(sPart + h2 * 2560 + tok * PPAD + g * 8 + 4);
            P0.x += v0.x; P0.y += v0.y; P0.z += v0.z; P0.w += v0.w;
            P1.x += v1.x; P1.y += v1.y; P1.z += v1.z; P1.w += v1.w;
        }
        float p[8] = {P0.x + sbf[8 * g + 0], P0.y + sbf[8 * g + 1],
                      P0.z + sbf[8 * g + 2], P0.w + sbf[8 * g + 3],
                      P1.x + sbf[8 * g + 4], P1.y + sbf[8 * g + 5],
                      P1.z + sbf[8 * g + 6], P1.w + sbf[8 * g + 7]};
        const float inv = 0.35355339059327376f;
        float cv[8], sv[8];
#pragma unroll
        for (int j = 0; j < 8; j++) {
            float s, c;
            __sincosf(p[j], &s, &c);
            cv[j] = c * inv; sv[j] = s * inv;
        }
        if (g == 0) {
            float4* qd = (float4*)(g_qP + (size_t)(row0 + tok) * F);
            qd[0] = make_float4(cv[0], cv[1], cv[2], cv[3]);
            qd[1] = make_float4(cv[4], cv[5], cv[6], cv[7]);
            qd[2] = make_float4(sv[0], sv[1], sv[2], sv[3]);
            qd[3] = make_float4(sv[4], sv[5], sv[6], sv[7]);
        } else {
            float4* kd = (float4*)(sKp + tok * KPAD);
            kd[0] = make_float4(cv[0], cv[1], cv[2], cv[3]);
            kd[1] = make_float4(cv[4], cv[5], cv[6], cv[7]);
            kd[2] = make_float4(sv[0], sv[1], sv[2], sv[3]);
            kd[3] = make_float4(sv[4], sv[5], sv[6], sv[7]);
        }
    }
    __syncthreads();

    // kpsum partial (deterministic), transposed layout
    if (tid < 16) {
        float s = 0.0f;
        for (int t = 0; t < CH; t++) s += sKp[t * KPAD + tid];
        g_kps[tid * NBLK + blk] = s;
    }

    // ---- pass 2: Gpart = Kp^T @ x_chunk, software-pipelined LDG ----
    uint64_t ga[8][4];
#pragma unroll
    for (int p2 = 0; p2 < 8; p2++)
#pragma unroll
        for (int c = 0; c < 4; c++) ga[p2][c] = 0ull;

    const float4* xp = (const float4*)(x + (size_t)row0 * E) + tid;

    float4 v0 = xp[0];
    float4 v1 = xp[E / 4];
#pragma unroll 4
    for (int t0 = 0; t0 < CH; t0 += 2) {
        float4 n0, n1;
        if (t0 < CH - 2) {
            n0 = xp[(size_t)(t0 + 2) * (E / 4)];
            n1 = xp[(size_t)(t0 + 3) * (E / 4)];
        }
#pragma unroll
        for (int u = 0; u < 2; u++) {
            const ulonglong2* kr = (const ulonglong2*)(sKp + (t0 + u) * KPAD);
            ulonglong2 k0 = kr[0], k1 = kr[1], k2 = kr[2], k3 = kr[3];
            uint64_t kp[8] = {k0.x, k0.y, k1.x, k1.y, k2.x, k2.y, k3.x, k3.y};
            float4 vv = u ? v1 : v0;
            float xa[4] = {vv.x, vv.y, vv.z, vv.w};
#pragma unroll
            for (int c = 0; c < 4; c++) {
                uint64_t xc = pack2(xa[c], xa[c]);
#pragma unroll
                for (int p2 = 0; p2 < 8; p2++) fma2(ga[p2][c], kp[p2], xc);
            }
        }
        v0 = n0; v1 = n1;
    }

    float* dst = g_Gpart + (size_t)blk * F * E + tid * 4;
#pragma unroll
    for (int p2 = 0; p2 < 8; p2++) {
        float2 u0 = unpack2(ga[p2][0]);
        float2 u1 = unpack2(ga[p2][1]);
        float2 u2 = unpack2(ga[p2][2]);
        float2 u3 = unpack2(ga[p2][3]);
        ((float4*)(dst + (size_t)(2 * p2) * E))[0]     = make_float4(u0.x, u1.x, u2.x, u3.x);
        ((float4*)(dst + (size_t)(2 * p2 + 1) * E))[0] = make_float4(u0.y, u1.y, u2.y, u3.y);
    }
}

// ============================================================
// k_sp: per (es,b,spg): reduce Gpart over 16 sp chunks for e-slice,
//       then Spart = Gslice @ Wv_slice.  grid (16,4,4), 128 thr.
// ============================================================
__global__ void __launch_bounds__(128) k_sp(const float* __restrict__ Wv) {
    int es  = blockIdx.x;
    int b   = blockIdx.y;
    int spg = blockIdx.z;
    int e0 = es * 64;
    int tid = threadIdx.x;
    __shared__ __align__(16) float sG[16][68];
    __shared__ __align__(16) float sWv[64][64];

    int f  = tid >> 3;
    int eo = (tid & 7) * 8;

    float4 a0 = make_float4(0.f, 0.f, 0.f, 0.f);
    float4 a1 = make_float4(0.f, 0.f, 0.f, 0.f);
    const float* base = g_Gpart + (size_t)(b * SPB + spg * 16) * (F * E) + (size_t)f * E + e0 + eo;
#pragma unroll 8
    for (int sp = 0; sp < 16; sp++) {
        const float4* p = (const float4*)(base + (size_t)sp * (F * E));
        float4 w0 = p[0], w1 = p[1];
        a0.x += w0.x; a0.y += w0.y; a0.z += w0.z; a0.w += w0.w;
        a1.x += w1.x; a1.y += w1.y; a1.z += w1.z; a1.w += w1.w;
    }
    *(float4*)&sG[f][eo]     = a0;
    *(float4*)&sG[f][eo + 4] = a1;

    const float4* wsrc = (const float4*)(Wv + (size_t)e0 * D);
    for (int i = tid; i < 64 * 16; i += 128)
        ((float4*)sWv)[i] = wsrc[i];
    __syncthreads();

    int dg = (tid & 7) * 8;
    float ac[8] = {0.f, 0.f, 0.f, 0.f, 0.f, 0.f, 0.f, 0.f};
#pragma unroll 4
    for (int e = 0; e < 64; e++) {
        float g = sG[f][e];
        float4 w0 = *(const float4*)&sWv[e][dg];
        float4 w1 = *(const float4*)&sWv[e][dg + 4];
        ac[0] += g * w0.x; ac[1] += g * w0.y; ac[2] += g * w0.z; ac[3] += g * w0.w;
        ac[4] += g * w1.x; ac[5] += g * w1.y; ac[6] += g * w1.z; ac[7] += g * w1.w;
    }
    float* dst = g_Spart + ((size_t)(spg * 16 + es) * B + b) * (F * D) + f * D + dg;
    *(float4*)dst       = make_float4(ac[0], ac[1], ac[2], ac[3]);
    *(float4*)(dst + 4) = make_float4(ac[4], ac[5], ac[6], ac[7]);
}

// ============================================================
// k_sfin: S[b,f,:] = sum_sl Spart + kpsum*bv.
// grid 64: block = (b = bid>>4, f = bid&15); 256 threads.
// ============================================================
__global__ void __launch_bounds__(256) k_sfin(const float* __restrict__ bv) {
    __shared__ __align__(16) float4 red[16][17];
    __shared__ float kw[2];
    int bid = blockIdx.x;
    int b = bid >> 4;
    int f = bid & 15;
    int tid = threadIdx.x;
    int s0 = tid >> 4;   // slice group 0..15
    int j  = tid & 15;   // d4 index

    // each thread sums 4 of the 64 slices for output float4 j
    const float4* sp4 = (const float4*)g_Spart;
    size_t o = (size_t)f * 16 + j + (size_t)b * 256;
    float4 a = sp4[((size_t)(s0)      * 4) * 256 + o];
    float4 c = sp4[((size_t)(s0 + 16) * 4) * 256 + o];
    float4 d = sp4[((size_t)(s0 + 32) * 4) * 256 + o];
    float4 e = sp4[((size_t)(s0 + 48) * 4) * 256 + o];
    a.x = (a.x + c.x) + (d.x + e.x);
    a.y = (a.y + c.y) + (d.y + e.y);
    a.z = (a.z + c.z) + (d.z + e.z);
    a.w = (a.w + c.w) + (d.w + e.w);
    red[s0][j] = a;

    // kpsum: 64 kps values for (f, batch b)
    if (tid < 64) {
        float v = g_kps[f * NBLK + b * 64 + tid];
#pragma unroll
        for (int off = 16; off > 0; off >>= 1)
            v += __shfl_xor_sync(0xffffffffu, v, off);
        if ((tid & 31) == 0) kw[tid >> 5] = v;
    }
    __syncthreads();

    if (tid < 16) {
        float4 s = red[0][tid];
#pragma unroll
        for (int g = 1; g < 16; g++) {
            float4 v = red[g][tid];
            s.x += v.x; s.y += v.y; s.z += v.z; s.w += v.w;
        }
        float kp = kw[0] + kw[1];
        float4 bvv = ((const float4*)bv)[tid];
        ((float4*)g_S)[(b * F + f) * 16 + tid] =
            make_float4(s.x + kp * bvv.x, s.y + kp * bvv.y,
                        s.z + kp * bvv.z, s.w + kp * bvv.w);
    }
}

// ============================================================
// k_y: y = qP @ S.  256 blocks x 256 thr, 128 tokens/block.
// ============================================================
__global__ void __launch_bounds__(256) k_y(float* __restrict__ y) {
    __shared__ __align__(16) float sS[F * D];
    int tid = threadIdx.x;
    int bid = blockIdx.x;
    int b = bid >> 6;
    ((float4*)sS)[tid] = ((const float4*)g_S)[b * 256 + tid];
    __syncthreads();

    int tl = tid & 127, g = tid >> 7;
    int t0 = bid * 128 + tl;

    const float4* qa = (const float4*)(g_qP + (size_t)t0 * F);
    float4 a0 = qa[0], a1 = qa[1], a2 = qa[2], a3 = qa[3];
    float qv[16] = {a0.x, a0.y, a0.z, a0.w, a1.x, a1.y, a1.z, a1.w,
                    a2.x, a2.y, a2.z, a2.w, a3.x, a3.y, a3.z, a3.w};

    uint64_t acc[16];
#pragma unroll
    for (int p = 0; p < 16; p++) acc[p] = 0ull;

#pragma unroll
    for (int f = 0; f < F; f++) {
        const ulonglong2* sr = (const ulonglong2*)(sS + f * D + g * 32);
        uint64_t qf = pack2(qv[f], qv[f]);
#pragma unroll
        for (int p = 0; p < 8; p++) {
            ulonglong2 w = sr[p];
            fma2(acc[2 * p],     qf, w.x);
            fma2(acc[2 * p + 1], qf, w.y);
        }
    }

    float4* dA = (float4*)(y + (size_t)t0 * D + g * 32);
#pragma unroll
    for (int p = 0; p < 8; p++) {
        float2 lo = unpack2(acc[2 * p]);
        float2 hi = unpack2(acc[2 * p + 1]);
        dA[p] = make_float4(lo.x, lo.y, hi.x, hi.y);
    }
}

// ============================================================
extern "C" void kernel_launch(void* const* d_in, const int* in_sizes, int n_in,
                              void* d_out, int out_size) {
    const float* x  = (const float*)d_in[0];
    const float* w  = (const float*)d_in[1];
    const float* Wq = (const float*)d_in[2];
    const float* bq = (const float*)d_in[3];
    const float* Wk = (const float*)d_in[4];
    const float* bk = (const float*)d_in[5];
    const float* Wv = (const float*)d_in[6];
    const float* bv = (const float*)d_in[7];
    float* y = (float*)d_out;

    cudaFuncSetAttribute(k_fused, cudaFuncAttributeMaxDynamicSharedMemorySize,
                         SMEM_FLOATS * 4);

    k_fold<<<64, 256>>>(Wq, bq, Wk, bk, w);
    k_fused<<<NBLK, 256, SMEM_FLOATS * 4>>>(x);
    dim3 gsp(16, 4, 4);
    k_sp<<<gsp, 128>>>(Wv);
    k_sfin<<<64, 256>>>(bv);
    k_y<<<256, 256>>>(y);
}